// round 10
// baseline (speedup 1.0000x reference)
#include <cuda_runtime.h>
#include <cuda_bf16.h>
#include <math.h>
#include <stdint.h>

#define NS 8192          /* B*S = 32*256 */
#define IN0 331

// ---------------- packed f32x2 helpers ----------------
__device__ __forceinline__ void ffma2(unsigned long long& d, unsigned long long a, unsigned long long b) {
    asm("fma.rn.f32x2 %0, %1, %2, %0;" : "+l"(d) : "l"(a), "l"(b));
}
__device__ __forceinline__ unsigned long long pack2(float x, float y) {
    unsigned long long r; asm("mov.b64 %0, {%1, %2};" : "=l"(r) : "f"(x), "f"(y)); return r;
}
__device__ __forceinline__ float2 unpk(unsigned long long v) {
    float2 f; asm("mov.b64 {%0, %1}, %2;" : "=f"(f.x), "=f"(f.y) : "l"(v)); return f;
}

// ---------------- barrier primitives ----------------
__device__ __forceinline__ unsigned ld_acq(const unsigned* p) {
    unsigned v; asm volatile("ld.acquire.gpu.global.u32 %0, [%1];" : "=r"(v) : "l"(p) : "memory"); return v;
}
__device__ __forceinline__ void st_rel(unsigned* p, unsigned v) {
    asm volatile("st.release.gpu.global.u32 [%0], %1;" :: "l"(p), "r"(v) : "memory");
}

// ---------------- mma helpers (sm_80-level PTX, compiles for compute_100) ----------------
__device__ __forceinline__ uint32_t smem_u32(const void* p) {
    uint32_t a; asm("{ .reg .u64 t; cvta.to.shared.u64 t, %1; cvt.u32.u64 %0, t; }" : "=r"(a) : "l"(p));
    return a;
}
__device__ __forceinline__ void ldmA(uint32_t* a, uint32_t saddr) {
    asm volatile("ldmatrix.sync.aligned.m8n8.x4.shared.b16 {%0,%1,%2,%3}, [%4];"
        : "=r"(a[0]), "=r"(a[1]), "=r"(a[2]), "=r"(a[3]) : "r"(saddr));
}
__device__ __forceinline__ void ldmBT(uint32_t* b, uint32_t saddr) {
    asm volatile("ldmatrix.sync.aligned.m8n8.x2.trans.shared.b16 {%0,%1}, [%2];"
        : "=r"(b[0]), "=r"(b[1]) : "r"(saddr));
}
__device__ __forceinline__ void mma16816(float* c, const uint32_t* a, const uint32_t* b) {
    asm volatile("mma.sync.aligned.m16n8k16.row.col.f32.bf16.bf16.f32 "
        "{%0,%1,%2,%3}, {%4,%5,%6,%7}, {%8,%9}, {%0,%1,%2,%3};"
        : "+f"(c[0]), "+f"(c[1]), "+f"(c[2]), "+f"(c[3])
        : "r"(a[0]), "r"(a[1]), "r"(a[2]), "r"(a[3]), "r"(b[0]), "r"(b[1]));
}
__device__ __forceinline__ void splitbf(float v, unsigned short& h, unsigned short& l) {
    __nv_bfloat16 bh = __float2bfloat16(v);
    __nv_bfloat16 bl = __float2bfloat16(v - __bfloat162float(bh));
    h = __bfloat16_as_ushort(bh);
    l = __bfloat16_as_ushort(bl);
}
__device__ __forceinline__ void cvt8(const float* v, uint4& hi, uint4& lo) {
    unsigned short h[8], l[8];
    #pragma unroll
    for (int e = 0; e < 8; e++) splitbf(v[e], h[e], l[e]);
    hi.x = (uint32_t)h[0] | ((uint32_t)h[1] << 16);
    hi.y = (uint32_t)h[2] | ((uint32_t)h[3] << 16);
    hi.z = (uint32_t)h[4] | ((uint32_t)h[5] << 16);
    hi.w = (uint32_t)h[6] | ((uint32_t)h[7] << 16);
    lo.x = (uint32_t)l[0] | ((uint32_t)l[1] << 16);
    lo.y = (uint32_t)l[2] | ((uint32_t)l[3] << 16);
    lo.z = (uint32_t)l[4] | ((uint32_t)l[5] << 16);
    lo.w = (uint32_t)l[6] | ((uint32_t)l[7] << 16);
}

// ---------------- static device scratch ----------------
__device__ float g_x[IN0 * NS];       // [k][m], m = s*32 + b
__device__ float g_preF[2048 * NS];   // [gate*512+h][m]
__device__ float g_preB[2048 * NS];
__device__ float g_out0[1024 * NS];   // [dir*512+h][m]
__device__ float g_out1[1024 * NS];
__device__ float g_h1[128 * NS];      // [k][m]
__device__ float g_hst[3 * 2 * 512 * 32];  // [buf3][dir][k][b]
__device__ float g_perb[32];
__device__ unsigned g_flag[128];      // [dir*64 + slot] step flags

// ---------------- embeddings + char CNN + concat + relu (writes x^T [k][m]) ----------------
__global__ void embed_cnn_kernel(const int* __restrict__ xw, const float* __restrict__ xpos,
                                 const int* __restrict__ xch, const float* __restrict__ xenr,
                                 const float* __restrict__ wemb, const float* __restrict__ cemb,
                                 const float* __restrict__ cnnW, const float* __restrict__ cnnb) {
    int n = blockIdx.x;              // b*256+s
    int b = n >> 8, s = n & 255;
    int m = s * 32 + b;
    __shared__ float ce[16][124];
    __shared__ float convs[32][12];
    __shared__ float cpool[32];
    __shared__ int   ch[16];
    int tid = threadIdx.x;
    int lane = tid & 31, w = tid >> 5;
    if (tid < 16) ch[tid] = xch[n * 16 + tid];
    __syncthreads();
    for (int i = tid; i < 16 * 124; i += 128) {
        int p = i / 124, c = i % 124;
        ce[p][c] = cemb[ch[p] * 124 + c];
    }
    __syncthreads();

    for (int og = w; og < 8; og += 4) {
        float Wr[4][4][5];
        #pragma unroll
        for (int cc = 0; cc < 4; cc++) {
            int c = lane + 32 * cc;
            #pragma unroll
            for (int oo = 0; oo < 4; oo++)
                #pragma unroll
                for (int k = 0; k < 5; k++)
                    Wr[oo][cc][k] = (c < 124) ? cnnW[(og * 4 + oo) * 620 + c * 5 + k] : 0.0f;
        }
        float cw[4][5];
        #pragma unroll
        for (int cc = 0; cc < 4; cc++) {
            int c = lane + 32 * cc;
            #pragma unroll
            for (int k = 0; k < 5; k++)
                cw[cc][k] = (c < 124) ? ce[k][c] : 0.0f;
        }
        for (int p = 0; p < 12; p++) {
            float acc[4] = {0.0f, 0.0f, 0.0f, 0.0f};
            #pragma unroll
            for (int oo = 0; oo < 4; oo++)
                #pragma unroll
                for (int cc = 0; cc < 4; cc++)
                    #pragma unroll
                    for (int k = 0; k < 5; k++)
                        acc[oo] += Wr[oo][cc][k] * cw[cc][k];
            #pragma unroll
            for (int oo = 0; oo < 4; oo++) {
                #pragma unroll
                for (int off = 16; off; off >>= 1)
                    acc[oo] += __shfl_xor_sync(0xffffffffu, acc[oo], off);
                if (lane == 0) convs[og * 4 + oo][p] = acc[oo] + cnnb[og * 4 + oo];
            }
            if (p < 11) {
                #pragma unroll
                for (int cc = 0; cc < 4; cc++) {
                    int c = lane + 32 * cc;
                    #pragma unroll
                    for (int k = 0; k < 4; k++) cw[cc][k] = cw[cc][k + 1];
                    cw[cc][4] = (c < 124) ? ce[p + 5][c] : 0.0f;
                }
            }
        }
    }
    __syncthreads();
    if (tid < 32) {
        float mx = convs[tid][0];
        #pragma unroll
        for (int p = 1; p < 12; p++) mx = fmaxf(mx, convs[tid][p]);
        cpool[tid] = mx;
    }
    __syncthreads();
    int widx = xw[n];
    for (int j = tid; j < IN0; j += 128) {
        float v;
        if      (j < 256) v = wemb[widx * 256 + j];
        else if (j < 292) v = xpos[n * 36 + (j - 256)];
        else if (j < 324) v = cpool[j - 292];
        else              v = xenr[n * 7 + (j - 324)];
        g_x[j * NS + m] = fmaxf(v, 0.0f);
    }
}

// ---------------- split-bf16 tensor GEMM (mma.sync, double-buffered) ----------------
// C[I][J] = W[I][K] @ X[K][J] + bias[I]. CTA 128x128, BK=32, 8 warps (2Mx4N).
// Dynamic smem: per buffer {Ahi(10240B) Alo(10240B) Bhi(8704B) Blo(8704B)} x2.
#define GA_HI 0
#define GA_LO 10240
#define GB_HI 20480
#define GB_LO 29184
#define GBUFB 37888
#define GEMM_SMEM (2 * GBUFB)

__global__ __launch_bounds__(256) void bgemm(
    const float* __restrict__ Wg, const float* __restrict__ Xg,
    const float* __restrict__ bias, float* __restrict__ C,
    int I, int J, int K
) {
    extern __shared__ __align__(16) char gsm[];
    uint32_t sbase = smem_u32(gsm);
    int tid = threadIdx.x, lane = tid & 31, wid = tid >> 5;
    int j0 = blockIdx.x * 128, i0 = blockIdx.y * 128;
    int wm = wid >> 2, wn = wid & 3;

    float acc[4][4][4];
    #pragma unroll
    for (int mt = 0; mt < 4; mt++)
        #pragma unroll
        for (int nt = 0; nt < 4; nt++)
            #pragma unroll
            for (int e = 0; e < 4; e++) acc[mt][nt][e] = 0.0f;

    // per-thread staging indices
    int arow[2], ak8[2], bkrow[2], bn8[2];
    #pragma unroll
    for (int it = 0; it < 2; it++) {
        int idx = it * 256 + tid;
        arow[it] = idx >> 2;  ak8[it] = (idx & 3) << 3;
        bkrow[it] = idx >> 4; bn8[it] = (idx & 15) << 3;
    }

    float vA[2][8], vB[2][8];
    int KB = (K + 31) >> 5;

    auto ldg_block = [&](int kb) {
        int kb32 = kb << 5;
        #pragma unroll
        for (int it = 0; it < 2; it++) {
            const float* wr = Wg + (size_t)(i0 + arow[it]) * K + kb32 + ak8[it];
            int rem = K - (kb32 + ak8[it]);
            #pragma unroll
            for (int e = 0; e < 8; e++) vA[it][e] = (e < rem) ? __ldg(wr + e) : 0.0f;
            int gk = kb32 + bkrow[it];
            if (gk < K) {
                const float* xr = Xg + (size_t)gk * J + j0 + bn8[it];
                float4 q0 = *(const float4*)xr;
                float4 q1 = *(const float4*)(xr + 4);
                vB[it][0] = q0.x; vB[it][1] = q0.y; vB[it][2] = q0.z; vB[it][3] = q0.w;
                vB[it][4] = q1.x; vB[it][5] = q1.y; vB[it][6] = q1.z; vB[it][7] = q1.w;
            } else {
                #pragma unroll
                for (int e = 0; e < 8; e++) vB[it][e] = 0.0f;
            }
        }
    };
    auto sts_block = [&](int buf) {
        char* base = gsm + buf * GBUFB;
        #pragma unroll
        for (int it = 0; it < 2; it++) {
            uint4 hi, lo;
            cvt8(vA[it], hi, lo);
            *(uint4*)(base + GA_HI + (arow[it] * 40 + ak8[it]) * 2) = hi;
            *(uint4*)(base + GA_LO + (arow[it] * 40 + ak8[it]) * 2) = lo;
            cvt8(vB[it], hi, lo);
            *(uint4*)(base + GB_HI + (bkrow[it] * 136 + bn8[it]) * 2) = hi;
            *(uint4*)(base + GB_LO + (bkrow[it] * 136 + bn8[it]) * 2) = lo;
        }
    };

    ldg_block(0);
    sts_block(0);
    __syncthreads();

    for (int kb = 0; kb < KB; kb++) {
        int buf = kb & 1;
        if (kb + 1 < KB) ldg_block(kb + 1);   // prefetch (hidden under compute)
        uint32_t ab = sbase + buf * GBUFB;
        uint32_t ah = ab + GA_HI, al = ab + GA_LO;
        uint32_t bh = ab + GB_HI, bl = ab + GB_LO;
        #pragma unroll
        for (int ks = 0; ks < 2; ks++) {
            uint32_t Ah[4][4], Al[4][4], Bh[4][2], Bl[4][2];
            #pragma unroll
            for (int mt = 0; mt < 4; mt++) {
                int row0 = wm * 64 + mt * 16;
                uint32_t off = (uint32_t)((row0 + (lane & 15)) * 40 + ks * 16 + ((lane >> 4) << 3)) * 2;
                ldmA(Ah[mt], ah + off);
                ldmA(Al[mt], al + off);
            }
            #pragma unroll
            for (int nt = 0; nt < 4; nt++) {
                int n0 = wn * 32 + nt * 8;
                uint32_t off = (uint32_t)((ks * 16 + (lane & 15)) * 136 + n0) * 2;
                ldmBT(Bh[nt], bh + off);
                ldmBT(Bl[nt], bl + off);
            }
            #pragma unroll
            for (int mt = 0; mt < 4; mt++)
                #pragma unroll
                for (int nt = 0; nt < 4; nt++) {
                    mma16816(acc[mt][nt], Ah[mt], Bh[nt]);
                    mma16816(acc[mt][nt], Ah[mt], Bl[nt]);
                    mma16816(acc[mt][nt], Al[mt], Bh[nt]);
                }
        }
        if (kb + 1 < KB) {
            sts_block(1 - buf);
            __syncthreads();
        }
    }
    // ---- epilogue ----
    int g = lane >> 2, q = lane & 3;
    #pragma unroll
    for (int mt = 0; mt < 4; mt++) {
        int r0 = i0 + wm * 64 + mt * 16 + g;
        float bv0 = __ldg(bias + r0), bv1 = __ldg(bias + r0 + 8);
        #pragma unroll
        for (int nt = 0; nt < 4; nt++) {
            int col = j0 + wn * 32 + nt * 8 + q * 2;
            float2 o0 = make_float2(acc[mt][nt][0] + bv0, acc[mt][nt][1] + bv0);
            float2 o1 = make_float2(acc[mt][nt][2] + bv1, acc[mt][nt][3] + bv1);
            *(float2*)&C[(size_t)r0 * J + col] = o0;
            *(float2*)&C[(size_t)(r0 + 8) * J + col] = o1;
        }
    }
}

// ---------------- LSTM reset: zero h buffer 0 + flags ----------------
__global__ void lstm_reset() {
    int idx = blockIdx.x * 1024 + threadIdx.x;
    if (idx < 32768) g_hst[idx] = 0.0f;
    if (idx < 128) g_flag[idx] = 0u;
}

// ---------------- persistent BiLSTM layer ----------------
__device__ __forceinline__ float sigf(float x) { return 1.0f / (1.0f + expf(-x)); }

// 128 blocks (dir = bx>>6, 8 h per block), 256 threads.
// Warp w = 64-k slice; each warp covers ALL 32 gate-rows (h read once per block).
__global__ void lstm_persistent(const float* __restrict__ preF, const float* __restrict__ preB,
                                const float* __restrict__ whhF, const float* __restrict__ whhB,
                                float* __restrict__ out) {
    extern __shared__ float sm[];
    float* Wsf = sm;                 // 16384 floats (64KB)
    float* zb  = sm + 16384;         // 8192 floats (32KB): [slice8][row32][b32]
    int tid = threadIdx.x;
    int lane = tid & 31, w = tid >> 5;
    int dir = blockIdx.x >> 6;
    int slot = blockIdx.x & 63;
    int h0 = slot * 8;
    const float* whh = dir ? whhB : whhF;
    const float* pre = dir ? preB : preF;
    unsigned* flg = &g_flag[dir * 64];

    // stage packed weights once: Ws4[kk2][rp] = {W[2rp][2kk2],W[2rp][2kk2+1],W[2rp+1][2kk2],W[2rp+1][2kk2+1]}
    for (int idx = tid; idx < 8192; idx += 256) {
        int kk2 = idx & 255, rp = (idx >> 8) & 15, e = idx >> 12;
        int r = 2 * rp + e;
        int grow = (r >> 3) * 512 + h0 + (r & 7);
        float2 wv = *(const float2*)&whh[grow * 512 + 2 * kk2];
        *(float2*)&Wsf[(kk2 * 16 + rp) * 4 + 2 * e] = wv;
    }
    float creg = 0.0f;
    int hl = tid >> 5, b = lane;

    float preg[4];
    {
        int t0 = dir ? 255 : 0;
        int m0 = t0 * 32 + b;
        #pragma unroll
        for (int g = 0; g < 4; g++) preg[g] = __ldg(&pre[(g * 512 + h0 + hl) * NS + m0]);
    }
    __syncthreads();

    const ulonglong2* WsV = (const ulonglong2*)Wsf;
    int buf = 0;
    for (int step = 0; step < 256; step++) {
        const float* hin = g_hst + buf * 32768 + dir * 16384;
        int nbuf = buf + 1; if (nbuf == 3) nbuf = 0;
        float* hout = g_hst + nbuf * 32768 + dir * 16384;

        // -------- recurrence: warp's 64-k slice, all 32 rows, h loaded ONCE --------
        const float* hsl = hin + w * 64 * 32;
        unsigned long long acc[32];
        #pragma unroll
        for (int i = 0; i < 32; i++) acc[i] = 0ull;

        float hb0[16], hb1[16];
        #pragma unroll
        for (int jj = 0; jj < 8; jj++) {
            hb0[2 * jj]     = __ldcg(hsl + jj * 64 + lane);
            hb0[2 * jj + 1] = __ldcg(hsl + jj * 64 + 32 + lane);
        }
        #pragma unroll
        for (int ch = 0; ch < 4; ch++) {
            float* cur = (ch & 1) ? hb1 : hb0;
            float* nxt = (ch & 1) ? hb0 : hb1;
            if (ch < 3) {
                const float* p = hsl + (ch + 1) * 8 * 64 + lane;
                #pragma unroll
                for (int jj = 0; jj < 8; jj++) {
                    nxt[2 * jj]     = __ldcg(p + jj * 64);
                    nxt[2 * jj + 1] = __ldcg(p + jj * 64 + 32);
                }
            }
            #pragma unroll
            for (int jj = 0; jj < 8; jj++) {
                unsigned long long hv = pack2(cur[2 * jj], cur[2 * jj + 1]);
                const ulonglong2* wp = WsV + ((w * 32 + ch * 8 + jj) << 4);
                #pragma unroll
                for (int rp = 0; rp < 16; rp++) {
                    ulonglong2 wv = wp[rp];
                    ffma2(acc[2 * rp],     wv.x, hv);
                    ffma2(acc[2 * rp + 1], wv.y, hv);
                }
            }
        }
        #pragma unroll
        for (int i = 0; i < 32; i++) {
            float2 f = unpk(acc[i]);
            zb[(w * 32 + i) * 32 + lane] = f.x + f.y;
        }
        __syncthreads();

        // -------- epilogue: thread = (hl, b) --------
        int t = dir ? 255 - step : step;
        int m = t * 32 + b;
        float z[4];
        #pragma unroll
        for (int g = 0; g < 4; g++) {
            int r = g * 8 + hl;
            float s = 0.0f;
            #pragma unroll
            for (int sl = 0; sl < 8; sl++) s += zb[(sl * 32 + r) * 32 + b];
            z[g] = s + preg[g];
        }
        float c = sigf(z[1]) * creg + sigf(z[0]) * tanhf(z[2]);
        float hn = sigf(z[3]) * tanhf(c);
        creg = c;
        int h = h0 + hl;
        __stcg(&hout[h * 32 + b], hn);
        __syncthreads();             // all hout stores done before arrive

        if (tid == 0 && step < 255) st_rel(&flg[slot], (unsigned)(step + 1));

        out[(dir * 512 + h) * NS + m] = hn;
        {
            int tn = dir ? 255 - (step + 1) : (step + 1);
            if (step == 255) tn = t;
            int mn = tn * 32 + b;
            #pragma unroll
            for (int g = 0; g < 4; g++) preg[g] = __ldg(&pre[(g * 512 + h0 + hl) * NS + mn]);
        }
        if (step < 255) {
            if (tid < 32) {
                unsigned target = (unsigned)(step + 1);
                for (;;) {
                    unsigned v0 = ld_acq(&flg[tid]);
                    unsigned v1 = ld_acq(&flg[32 + tid]);
                    if (__all_sync(0xffffffffu, (v0 >= target) && (v1 >= target))) break;
                }
            }
            __syncthreads();
        }
        buf = nbuf;
    }
}

// ---------------- lin2: em[n][18] from h1[k][m] ----------------
__global__ void lin2_kernel(const float* __restrict__ h1, const float* __restrict__ W,
                            const float* __restrict__ bias, float* __restrict__ em) {
    __shared__ float row[128];
    int mm = blockIdx.x, tid = threadIdx.x;
    int s = mm >> 5, b = mm & 31;
    for (int i = tid; i < 128; i += 32) row[i] = h1[i * NS + mm];
    __syncwarp();
    if (tid < 18) {
        float acc = bias[tid];
        for (int k = 0; k < 128; k++) acc += row[k] * W[tid * 128 + k];
        em[(b * 256 + s) * 18 + tid] = acc;
    }
}

// ---------------- CRF: forward logZ + NLL numerator + Viterbi, per batch ----------------
__global__ void crf_kernel(const float* __restrict__ em, const int* __restrict__ y,
                           const float* __restrict__ cstart, const float* __restrict__ cend,
                           const float* __restrict__ ctrans,
                           float* __restrict__ dec_out, float* __restrict__ perb) {
    __shared__ float tr[324];
    __shared__ float sc[18], fs[18];
    __shared__ int hist[255][18];
    __shared__ int dec[256];
    int b = blockIdx.x, j = threadIdx.x;
    for (int i = j; i < 324; i += 32) tr[i] = ctrans[i];
    const float* emb = em + b * 256 * 18;
    if (j < 18) { float v = cstart[j] + emb[j]; sc[j] = v; fs[j] = v; }
    __syncwarp();
    for (int s = 1; s < 256; s++) {
        float bestv = -1e30f, m = -1e30f, e = 0.0f, ssum = 0.0f;
        int bi = 0;
        if (j < 18) {
            e = emb[s * 18 + j];
            #pragma unroll
            for (int i = 0; i < 18; i++) {
                float t1 = sc[i] + tr[i * 18 + j];
                if (t1 > bestv) { bestv = t1; bi = i; }
                float t2 = fs[i] + tr[i * 18 + j];
                m = fmaxf(m, t2);
            }
            #pragma unroll
            for (int i = 0; i < 18; i++) ssum += expf(fs[i] + tr[i * 18 + j] - m);
        }
        __syncwarp();
        if (j < 18) {
            sc[j] = bestv + e;
            fs[j] = m + logf(ssum) + e;
            hist[s - 1][j] = bi;
        }
        __syncwarp();
    }
    float v = (j < 18) ? fs[j] + cend[j] : -1e30f;
    float m = v;
    for (int o = 16; o; o >>= 1) m = fmaxf(m, __shfl_xor_sync(0xffffffffu, m, o));
    float ex = (j < 18) ? expf(v - m) : 0.0f;
    for (int o = 16; o; o >>= 1) ex += __shfl_xor_sync(0xffffffffu, ex, o);
    float logZ = m + logf(ex);

    if (j == 0) {
        float best = -1e30f; int last = 0;
        for (int t2 = 0; t2 < 18; t2++) {
            float vv = sc[t2] + cend[t2];
            if (vv > best) { best = vv; last = t2; }
        }
        dec[255] = last;
        int tag = last;
        for (int s = 254; s >= 0; s--) { tag = hist[s][tag]; dec[s] = tag; }
        const int* yb = y + b * 256;
        float num = cstart[yb[0]] + emb[yb[0]];
        for (int s = 1; s < 256; s++) num += tr[yb[s-1] * 18 + yb[s]] + emb[s * 18 + yb[s]];
        num += cend[yb[255]];
        perb[b] = num - logZ;
    }
    __syncwarp();
    for (int s = j; s < 256; s += 32) dec_out[b * 256 + s] = (float)dec[s];
}

__global__ void loss_kernel(const float* __restrict__ perb, float* __restrict__ lossp) {
    if (threadIdx.x == 0) {
        float s = 0.0f;
        for (int b = 0; b < 32; b++) s += perb[b];
        *lossp = -s / 8192.0f;
    }
}

// ---------------- launch ----------------
#define LSTM_SMEM ((16384 + 8192) * 4)

extern "C" void kernel_launch(void* const* d_in, const int* in_sizes, int n_in,
                              void* d_out, int out_size) {
    (void)in_sizes; (void)n_in; (void)out_size;
    const int*   xw   = (const int*)d_in[0];
    const float* xpos = (const float*)d_in[1];
    const int*   xch  = (const int*)d_in[2];
    const float* xenr = (const float*)d_in[3];
    /* d_in[4] = mask (all ones, folded out) */
    const int*   yw   = (const int*)d_in[5];
    const float* wemb = (const float*)d_in[6];
    const float* cemb = (const float*)d_in[7];
    const float* cnnW = (const float*)d_in[8];
    const float* cnnb = (const float*)d_in[9];
    const float* lin1W = (const float*)d_in[10];
    const float* lin1b = (const float*)d_in[11];
    const float* lin2W = (const float*)d_in[12];
    const float* lin2b = (const float*)d_in[13];
    const float* cst  = (const float*)d_in[14];
    const float* cen  = (const float*)d_in[15];
    const float* ctr  = (const float*)d_in[16];
    const float* w0fI = (const float*)d_in[17];
    const float* w0fH = (const float*)d_in[18];
    const float* b0f  = (const float*)d_in[19];
    const float* w0bI = (const float*)d_in[20];
    const float* w0bH = (const float*)d_in[21];
    const float* b0b  = (const float*)d_in[22];
    const float* w1fI = (const float*)d_in[23];
    const float* w1fH = (const float*)d_in[24];
    const float* b1f  = (const float*)d_in[25];
    const float* w1bI = (const float*)d_in[26];
    const float* w1bH = (const float*)d_in[27];
    const float* b1b  = (const float*)d_in[28];
    float* out = (float*)d_out;

    cudaFuncSetAttribute(lstm_persistent, cudaFuncAttributeMaxDynamicSharedMemorySize, LSTM_SMEM);
    cudaFuncSetAttribute(bgemm, cudaFuncAttributeMaxDynamicSharedMemorySize, GEMM_SMEM);

    float *px, *pF, *pB, *po0, *po1, *ph1, *pperb;
    cudaGetSymbolAddress((void**)&px,    g_x);
    cudaGetSymbolAddress((void**)&pF,    g_preF);
    cudaGetSymbolAddress((void**)&pB,    g_preB);
    cudaGetSymbolAddress((void**)&po0,   g_out0);
    cudaGetSymbolAddress((void**)&po1,   g_out1);
    cudaGetSymbolAddress((void**)&ph1,   g_h1);
    cudaGetSymbolAddress((void**)&pperb, g_perb);

    embed_cnn_kernel<<<NS, 128>>>(xw, xpos, xch, xenr, wemb, cemb, cnnW, cnnb);

    // layer0 input projections: [2048 x 331] @ [331 x 8192]
    bgemm<<<dim3(64, 16), 256, GEMM_SMEM>>>(w0fI, px, b0f, pF, 2048, NS, IN0);
    bgemm<<<dim3(64, 16), 256, GEMM_SMEM>>>(w0bI, px, b0b, pB, 2048, NS, IN0);
    lstm_reset<<<32, 1024>>>();
    lstm_persistent<<<128, 256, LSTM_SMEM>>>(pF, pB, w0fH, w0bH, po0);

    // layer1 input projections: [2048 x 1024] @ [1024 x 8192]
    bgemm<<<dim3(64, 16), 256, GEMM_SMEM>>>(w1fI, po0, b1f, pF, 2048, NS, 1024);
    bgemm<<<dim3(64, 16), 256, GEMM_SMEM>>>(w1bI, po0, b1b, pB, 2048, NS, 1024);
    lstm_reset<<<32, 1024>>>();
    lstm_persistent<<<128, 256, LSTM_SMEM>>>(pF, pB, w1fH, w1bH, po1);

    // heads
    bgemm<<<dim3(64, 1), 256, GEMM_SMEM>>>(lin1W, po1, lin1b, ph1, 128, NS, 1024);
    lin2_kernel<<<NS, 32>>>(ph1, lin2W, lin2b, out);

    // CRF: em at out[0..147456), decoded at out[147456..155648), loss at out[155648]
    crf_kernel<<<32, 32>>>(out, yw, cst, cen, ctr, out + 147456, pperb);
    loss_kernel<<<1, 32>>>(pperb, out + 147456 + 8192);
}

// round 11
// speedup vs baseline: 1.2162x; 1.2162x over previous
#include <cuda_runtime.h>
#include <cuda_bf16.h>
#include <math.h>
#include <stdint.h>

#define NS 8192          /* B*S = 32*256 */
#define IN0 331
#define IN0P 352         /* IN0 padded to 32 */

// ---------------- packed f32x2 helpers ----------------
__device__ __forceinline__ void ffma2(unsigned long long& d, unsigned long long a, unsigned long long b) {
    asm("fma.rn.f32x2 %0, %1, %2, %0;" : "+l"(d) : "l"(a), "l"(b));
}
__device__ __forceinline__ unsigned long long pack2(float x, float y) {
    unsigned long long r; asm("mov.b64 %0, {%1, %2};" : "=l"(r) : "f"(x), "f"(y)); return r;
}
__device__ __forceinline__ float2 unpk(unsigned long long v) {
    float2 f; asm("mov.b64 {%0, %1}, %2;" : "=f"(f.x), "=f"(f.y) : "l"(v)); return f;
}

// ---------------- barrier primitives ----------------
__device__ __forceinline__ unsigned ld_acq(const unsigned* p) {
    unsigned v; asm volatile("ld.acquire.gpu.global.u32 %0, [%1];" : "=r"(v) : "l"(p) : "memory"); return v;
}
__device__ __forceinline__ void st_rel(unsigned* p, unsigned v) {
    asm volatile("st.release.gpu.global.u32 [%0], %1;" :: "l"(p), "r"(v) : "memory");
}

// ---------------- mma helpers ----------------
__device__ __forceinline__ uint32_t smem_u32(const void* p) {
    uint32_t a; asm("{ .reg .u64 t; cvta.to.shared.u64 t, %1; cvt.u32.u64 %0, t; }" : "=r"(a) : "l"(p));
    return a;
}
__device__ __forceinline__ void ldmA(uint32_t* a, uint32_t saddr) {
    asm volatile("ldmatrix.sync.aligned.m8n8.x4.shared.b16 {%0,%1,%2,%3}, [%4];"
        : "=r"(a[0]), "=r"(a[1]), "=r"(a[2]), "=r"(a[3]) : "r"(saddr));
}
__device__ __forceinline__ void ldmBT(uint32_t* b, uint32_t saddr) {
    asm volatile("ldmatrix.sync.aligned.m8n8.x2.trans.shared.b16 {%0,%1}, [%2];"
        : "=r"(b[0]), "=r"(b[1]) : "r"(saddr));
}
__device__ __forceinline__ void mma16816(float* c, const uint32_t* a, const uint32_t* b) {
    asm volatile("mma.sync.aligned.m16n8k16.row.col.f32.bf16.bf16.f32 "
        "{%0,%1,%2,%3}, {%4,%5,%6,%7}, {%8,%9}, {%0,%1,%2,%3};"
        : "+f"(c[0]), "+f"(c[1]), "+f"(c[2]), "+f"(c[3])
        : "r"(a[0]), "r"(a[1]), "r"(a[2]), "r"(a[3]), "r"(b[0]), "r"(b[1]));
}

// ---------------- static device scratch ----------------
__device__ float g_x[IN0 * NS];       // [k][m], m = s*32 + b
__device__ float g_preF[2048 * NS];   // [gate*512+h][m]
__device__ float g_preB[2048 * NS];
__device__ float g_out0[1024 * NS];   // [dir*512+h][m]
__device__ float g_out1[1024 * NS];
__device__ float g_h1[128 * NS];      // [k][m]
__device__ float g_hst[3 * 2 * 512 * 32];  // [buf3][dir][k][b]
__device__ float g_perb[32];
__device__ unsigned g_flag[128];      // [dir*64 + slot] step flags
// pre-split bf16 GEMM operands (padded K)
__device__ __nv_bfloat16 g_wah[2048 * 1024], g_wal[2048 * 1024];  // dir-A weights
__device__ __nv_bfloat16 g_wbh[2048 * 1024], g_wbl[2048 * 1024];  // dir-B weights
__device__ __nv_bfloat16 g_xh[1024 * NS],   g_xl[1024 * NS];      // X operand

// ---------------- conversion kernels (fp32 -> bf16 hi/lo, padded) ----------------
__global__ void cvt_w(const float* __restrict__ src, __nv_bfloat16* __restrict__ hi,
                      __nv_bfloat16* __restrict__ lo, int K, int Kp) {
    int row = blockIdx.y;
    int k = blockIdx.x * 256 + threadIdx.x;
    if (k >= Kp) return;
    float v = (k < K) ? src[row * K + k] : 0.0f;
    __nv_bfloat16 h = __float2bfloat16(v);
    __nv_bfloat16 l = __float2bfloat16(v - __bfloat162float(h));
    hi[row * Kp + k] = h;
    lo[row * Kp + k] = l;
}
__global__ void cvt_x(const float* __restrict__ src, __nv_bfloat16* __restrict__ hi,
                      __nv_bfloat16* __restrict__ lo, int K) {
    int row = blockIdx.y;
    int col = blockIdx.x * 256 + threadIdx.x;
    float v = (row < K) ? src[row * NS + col] : 0.0f;
    __nv_bfloat16 h = __float2bfloat16(v);
    __nv_bfloat16 l = __float2bfloat16(v - __bfloat162float(h));
    hi[row * NS + col] = h;
    lo[row * NS + col] = l;
}

// ---------------- embeddings + char CNN + concat + relu (writes x^T [k][m]) ----------------
__global__ void embed_cnn_kernel(const int* __restrict__ xw, const float* __restrict__ xpos,
                                 const int* __restrict__ xch, const float* __restrict__ xenr,
                                 const float* __restrict__ wemb, const float* __restrict__ cemb,
                                 const float* __restrict__ cnnW, const float* __restrict__ cnnb) {
    int n = blockIdx.x;              // b*256+s
    int b = n >> 8, s = n & 255;
    int m = s * 32 + b;
    __shared__ float ce[16][124];
    __shared__ float convs[32][12];
    __shared__ float cpool[32];
    __shared__ int   ch[16];
    int tid = threadIdx.x;
    int lane = tid & 31, w = tid >> 5;
    if (tid < 16) ch[tid] = xch[n * 16 + tid];
    __syncthreads();
    for (int i = tid; i < 16 * 124; i += 128) {
        int p = i / 124, c = i % 124;
        ce[p][c] = cemb[ch[p] * 124 + c];
    }
    __syncthreads();

    for (int og = w; og < 8; og += 4) {
        float Wr[4][4][5];
        #pragma unroll
        for (int cc = 0; cc < 4; cc++) {
            int c = lane + 32 * cc;
            #pragma unroll
            for (int oo = 0; oo < 4; oo++)
                #pragma unroll
                for (int k = 0; k < 5; k++)
                    Wr[oo][cc][k] = (c < 124) ? cnnW[(og * 4 + oo) * 620 + c * 5 + k] : 0.0f;
        }
        float cw[4][5];
        #pragma unroll
        for (int cc = 0; cc < 4; cc++) {
            int c = lane + 32 * cc;
            #pragma unroll
            for (int k = 0; k < 5; k++)
                cw[cc][k] = (c < 124) ? ce[k][c] : 0.0f;
        }
        for (int p = 0; p < 12; p++) {
            float acc[4] = {0.0f, 0.0f, 0.0f, 0.0f};
            #pragma unroll
            for (int oo = 0; oo < 4; oo++)
                #pragma unroll
                for (int cc = 0; cc < 4; cc++)
                    #pragma unroll
                    for (int k = 0; k < 5; k++)
                        acc[oo] += Wr[oo][cc][k] * cw[cc][k];
            #pragma unroll
            for (int oo = 0; oo < 4; oo++) {
                #pragma unroll
                for (int off = 16; off; off >>= 1)
                    acc[oo] += __shfl_xor_sync(0xffffffffu, acc[oo], off);
                if (lane == 0) convs[og * 4 + oo][p] = acc[oo] + cnnb[og * 4 + oo];
            }
            if (p < 11) {
                #pragma unroll
                for (int cc = 0; cc < 4; cc++) {
                    int c = lane + 32 * cc;
                    #pragma unroll
                    for (int k = 0; k < 4; k++) cw[cc][k] = cw[cc][k + 1];
                    cw[cc][4] = (c < 124) ? ce[p + 5][c] : 0.0f;
                }
            }
        }
    }
    __syncthreads();
    if (tid < 32) {
        float mx = convs[tid][0];
        #pragma unroll
        for (int p = 1; p < 12; p++) mx = fmaxf(mx, convs[tid][p]);
        cpool[tid] = mx;
    }
    __syncthreads();
    int widx = xw[n];
    for (int j = tid; j < IN0; j += 128) {
        float v;
        if      (j < 256) v = wemb[widx * 256 + j];
        else if (j < 292) v = xpos[n * 36 + (j - 256)];
        else if (j < 324) v = cpool[j - 292];
        else              v = xenr[n * 7 + (j - 324)];
        g_x[j * NS + m] = fmaxf(v, 0.0f);
    }
}

// ---------------- split-bf16 tensor GEMM (pre-split operands, fused F/B via grid.z) ----------
// C[I][J] = W[I][Kp] @ X[Kp][J] + bias[I]. CTA 128x128, BK=32, 8 warps (2Mx4N).
__global__ __launch_bounds__(256) void bgemm(
    const __nv_bfloat16* __restrict__ WhA, const __nv_bfloat16* __restrict__ WlA,
    const float* __restrict__ biasA, float* __restrict__ CA,
    const __nv_bfloat16* __restrict__ WhB, const __nv_bfloat16* __restrict__ WlB,
    const float* __restrict__ biasB, float* __restrict__ CB,
    int J, int Kp
) {
    __shared__ __align__(16) unsigned short As[2][128 * 40];   // hi, lo (stride 40)
    __shared__ __align__(16) unsigned short Bs[2][32 * 136];   // hi, lo (stride 136)
    int tid = threadIdx.x, lane = tid & 31, wid = tid >> 5;
    int j0 = blockIdx.x * 128, i0 = blockIdx.y * 128;
    int wm = wid >> 2, wn = wid & 3;
    const __nv_bfloat16* Wh = blockIdx.z ? WhB : WhA;
    const __nv_bfloat16* Wl = blockIdx.z ? WlB : WlA;
    const float* bias = blockIdx.z ? biasB : biasA;
    float* C = blockIdx.z ? CB : CA;

    float acc[4][4][4];
    #pragma unroll
    for (int mt = 0; mt < 4; mt++)
        #pragma unroll
        for (int nt = 0; nt < 4; nt++)
            #pragma unroll
            for (int e = 0; e < 4; e++) acc[mt][nt][e] = 0.0f;

    uint32_t asb0 = smem_u32(As[0]), asb1 = smem_u32(As[1]);
    uint32_t bsb0 = smem_u32(Bs[0]), bsb1 = smem_u32(Bs[1]);

    int KB = Kp >> 5;
    for (int kb = 0; kb < KB; kb++) {
        int kb32 = kb << 5;
        // ---- stage A: 128 rows x 32 k, pure LDG.128 -> STS.128 ----
        #pragma unroll
        for (int it = 0; it < 2; it++) {
            int idx = it * 256 + tid;
            int row = idx >> 2, k8 = (idx & 3) << 3;
            size_t go = (size_t)(i0 + row) * Kp + kb32 + k8;
            *(uint4*)&As[0][row * 40 + k8] = *(const uint4*)(Wh + go);
            *(uint4*)&As[1][row * 40 + k8] = *(const uint4*)(Wl + go);
        }
        // ---- stage B: 32 k-rows x 128 n ----
        #pragma unroll
        for (int it = 0; it < 2; it++) {
            int idx = it * 256 + tid;
            int krow = idx >> 4, n8 = (idx & 15) << 3;
            size_t go = (size_t)(kb32 + krow) * J + j0 + n8;
            *(uint4*)&Bs[0][krow * 136 + n8] = *(const uint4*)(g_xh + go);
            *(uint4*)&Bs[1][krow * 136 + n8] = *(const uint4*)(g_xl + go);
        }
        __syncthreads();
        // ---- compute: 2 k16 steps, 3 terms ----
        #pragma unroll
        for (int ks = 0; ks < 2; ks++) {
            uint32_t Ah[4][4], Al[4][4], Bh[4][2], Bl[4][2];
            #pragma unroll
            for (int mt = 0; mt < 4; mt++) {
                int row0 = wm * 64 + mt * 16;
                uint32_t off = (uint32_t)((row0 + (lane & 15)) * 40 + ks * 16 + ((lane >> 4) << 3)) * 2;
                ldmA(Ah[mt], asb0 + off);
                ldmA(Al[mt], asb1 + off);
            }
            #pragma unroll
            for (int nt = 0; nt < 4; nt++) {
                int n0 = wn * 32 + nt * 8;
                uint32_t off = (uint32_t)((ks * 16 + (lane & 15)) * 136 + n0) * 2;
                ldmBT(Bh[nt], bsb0 + off);
                ldmBT(Bl[nt], bsb1 + off);
            }
            #pragma unroll
            for (int mt = 0; mt < 4; mt++)
                #pragma unroll
                for (int nt = 0; nt < 4; nt++) {
                    mma16816(acc[mt][nt], Ah[mt], Bh[nt]);
                    mma16816(acc[mt][nt], Ah[mt], Bl[nt]);
                    mma16816(acc[mt][nt], Al[mt], Bh[nt]);
                }
        }
        __syncthreads();
    }
    // ---- epilogue ----
    int g = lane >> 2, q = lane & 3;
    #pragma unroll
    for (int mt = 0; mt < 4; mt++) {
        int r0 = i0 + wm * 64 + mt * 16 + g;
        float bv0 = __ldg(bias + r0), bv1 = __ldg(bias + r0 + 8);
        #pragma unroll
        for (int nt = 0; nt < 4; nt++) {
            int col = j0 + wn * 32 + nt * 8 + q * 2;
            float2 o0 = make_float2(acc[mt][nt][0] + bv0, acc[mt][nt][1] + bv0);
            float2 o1 = make_float2(acc[mt][nt][2] + bv1, acc[mt][nt][3] + bv1);
            *(float2*)&C[(size_t)r0 * J + col] = o0;
            *(float2*)&C[(size_t)(r0 + 8) * J + col] = o1;
        }
    }
}

// ---------------- LSTM reset: zero h buffer 0 + flags ----------------
__global__ void lstm_reset() {
    int idx = blockIdx.x * 1024 + threadIdx.x;
    if (idx < 32768) g_hst[idx] = 0.0f;
    if (idx < 128) g_flag[idx] = 0u;
}

// ---------------- persistent BiLSTM layer (R9-exact, proven config) ----------------
__device__ __forceinline__ float sigf(float x) { return 1.0f / (1.0f + expf(-x)); }

__global__ void lstm_persistent(const float* __restrict__ preF, const float* __restrict__ preB,
                                const float* __restrict__ whhF, const float* __restrict__ whhB,
                                float* __restrict__ out) {
    extern __shared__ float sm[];
    float* Wsf = sm;                 // 16384 floats (64KB)
    float* zb  = sm + 16384;         // 4096 floats (16KB)
    int tid = threadIdx.x;
    int lane = tid & 31, w = tid >> 5;
    int ks = w >> 1, rg = w & 1;
    int dir = blockIdx.x >> 6;
    int slot = blockIdx.x & 63;
    int h0 = slot * 8;
    const float* whh = dir ? whhB : whhF;
    const float* pre = dir ? preB : preF;
    unsigned* flg = &g_flag[dir * 64];

    for (int idx = tid; idx < 8192; idx += 256) {
        int kk2 = idx & 255, rp = (idx >> 8) & 15, e = idx >> 12;
        int r = 2 * rp + e;
        int grow = (r >> 3) * 512 + h0 + (r & 7);
        float2 wv = *(const float2*)&whh[grow * 512 + 2 * kk2];
        *(float2*)&Wsf[(kk2 * 16 + rp) * 4 + 2 * e] = wv;
    }
    float creg = 0.0f;
    int hl = tid >> 5, b = lane;

    float preg[4];
    {
        int t0 = dir ? 255 : 0;
        int m0 = t0 * 32 + b;
        #pragma unroll
        for (int g = 0; g < 4; g++) preg[g] = __ldg(&pre[(g * 512 + h0 + hl) * NS + m0]);
    }
    __syncthreads();

    const ulonglong2* WsV = (const ulonglong2*)Wsf;
    int buf = 0;
    for (int step = 0; step < 256; step++) {
        const float* hin = g_hst + buf * 32768 + dir * 16384;
        int nbuf = buf + 1; if (nbuf == 3) nbuf = 0;
        float* hout = g_hst + nbuf * 32768 + dir * 16384;

        const float* hsl = hin + ks * 128 * 32;
        unsigned long long acc[16];
        #pragma unroll
        for (int i = 0; i < 16; i++) acc[i] = 0ull;

        float hb0[16], hb1[16];
        #pragma unroll
        for (int jj = 0; jj < 8; jj++) {
            hb0[2 * jj]     = __ldcg(hsl + jj * 64 + lane);
            hb0[2 * jj + 1] = __ldcg(hsl + jj * 64 + 32 + lane);
        }
        #pragma unroll
        for (int ch = 0; ch < 8; ch++) {
            float* cur = (ch & 1) ? hb1 : hb0;
            float* nxt = (ch & 1) ? hb0 : hb1;
            if (ch < 7) {
                const float* p = hsl + (ch + 1) * 8 * 64 + lane;
                #pragma unroll
                for (int jj = 0; jj < 8; jj++) {
                    nxt[2 * jj]     = __ldcg(p + jj * 64);
                    nxt[2 * jj + 1] = __ldcg(p + jj * 64 + 32);
                }
            }
            #pragma unroll
            for (int jj = 0; jj < 8; jj++) {
                unsigned long long hv = pack2(cur[2 * jj], cur[2 * jj + 1]);
                const ulonglong2* wp = WsV + ((ks * 64 + ch * 8 + jj) << 4) + rg * 8;
                #pragma unroll
                for (int rp = 0; rp < 8; rp++) {
                    ulonglong2 wv = wp[rp];
                    ffma2(acc[2 * rp],     wv.x, hv);
                    ffma2(acc[2 * rp + 1], wv.y, hv);
                }
            }
        }
        #pragma unroll
        for (int i = 0; i < 16; i++) {
            float2 f = unpk(acc[i]);
            zb[(ks * 32 + rg * 16 + i) * 32 + lane] = f.x + f.y;
        }
        __syncthreads();

        int t = dir ? 255 - step : step;
        int m = t * 32 + b;
        float z[4];
        #pragma unroll
        for (int g = 0; g < 4; g++) {
            int r = g * 8 + hl;
            z[g] = zb[(0 * 32 + r) * 32 + b] + zb[(1 * 32 + r) * 32 + b]
                 + zb[(2 * 32 + r) * 32 + b] + zb[(3 * 32 + r) * 32 + b] + preg[g];
        }
        float c = sigf(z[1]) * creg + sigf(z[0]) * tanhf(z[2]);
        float hn = sigf(z[3]) * tanhf(c);
        creg = c;
        int h = h0 + hl;
        __stcg(&hout[h * 32 + b], hn);
        __syncthreads();

        if (tid == 0 && step < 255) st_rel(&flg[slot], (unsigned)(step + 1));

        out[(dir * 512 + h) * NS + m] = hn;
        {
            int tn = dir ? 255 - (step + 1) : (step + 1);
            if (step == 255) tn = t;
            int mn = tn * 32 + b;
            #pragma unroll
            for (int g = 0; g < 4; g++) preg[g] = __ldg(&pre[(g * 512 + h0 + hl) * NS + mn]);
        }
        if (step < 255) {
            if (tid < 32) {
                unsigned target = (unsigned)(step + 1);
                for (;;) {
                    unsigned v0 = ld_acq(&flg[tid]);
                    unsigned v1 = ld_acq(&flg[32 + tid]);
                    if (__all_sync(0xffffffffu, (v0 >= target) && (v1 >= target))) break;
                }
            }
            __syncthreads();
        }
        buf = nbuf;
    }
}

// ---------------- lin2: 4 m per block, transposed W in smem ----------------
__global__ void lin2_kernel(const float* __restrict__ h1, const float* __restrict__ W,
                            const float* __restrict__ bias, float* __restrict__ em) {
    __shared__ float Wt[128 * 18];
    __shared__ float rows[4][128];
    int tid = threadIdx.x, lane = tid & 31, w = tid >> 5;
    for (int idx = tid; idx < 2304; idx += 128) {
        int o = idx >> 7, k = idx & 127;
        Wt[k * 18 + o] = W[idx];
    }
    int mm = blockIdx.x * 4 + w;
    for (int i = lane; i < 128; i += 32) rows[w][i] = h1[i * NS + mm];
    __syncthreads();
    if (lane < 18) {
        float acc = bias[lane];
        #pragma unroll 8
        for (int k = 0; k < 128; k++) acc += rows[w][k] * Wt[k * 18 + lane];
        int s = mm >> 5, b = mm & 31;
        em[(b * 256 + s) * 18 + lane] = acc;
    }
}

// ---------------- CRF: forward logZ + NLL numerator + Viterbi, per batch ----------------
__global__ void crf_kernel(const float* __restrict__ em, const int* __restrict__ y,
                           const float* __restrict__ cstart, const float* __restrict__ cend,
                           const float* __restrict__ ctrans,
                           float* __restrict__ dec_out, float* __restrict__ perb) {
    __shared__ float tr[324];
    __shared__ float sc[18], fs[18];
    __shared__ int hist[255][18];
    __shared__ int dec[256];
    int b = blockIdx.x, j = threadIdx.x;
    for (int i = j; i < 324; i += 32) tr[i] = ctrans[i];
    const float* emb = em + b * 256 * 18;
    if (j < 18) { float v = cstart[j] + emb[j]; sc[j] = v; fs[j] = v; }
    __syncwarp();
    for (int s = 1; s < 256; s++) {
        float bestv = -1e30f, m = -1e30f, e = 0.0f, ssum = 0.0f;
        int bi = 0;
        if (j < 18) {
            e = emb[s * 18 + j];
            #pragma unroll
            for (int i = 0; i < 18; i++) {
                float t1 = sc[i] + tr[i * 18 + j];
                if (t1 > bestv) { bestv = t1; bi = i; }
                float t2 = fs[i] + tr[i * 18 + j];
                m = fmaxf(m, t2);
            }
            #pragma unroll
            for (int i = 0; i < 18; i++) ssum += __expf(fs[i] + tr[i * 18 + j] - m);
        }
        __syncwarp();
        if (j < 18) {
            sc[j] = bestv + e;
            fs[j] = m + __logf(ssum) + e;
            hist[s - 1][j] = bi;
        }
        __syncwarp();
    }
    float v = (j < 18) ? fs[j] + cend[j] : -1e30f;
    float m = v;
    for (int o = 16; o; o >>= 1) m = fmaxf(m, __shfl_xor_sync(0xffffffffu, m, o));
    float ex = (j < 18) ? __expf(v - m) : 0.0f;
    for (int o = 16; o; o >>= 1) ex += __shfl_xor_sync(0xffffffffu, ex, o);
    float logZ = m + __logf(ex);

    if (j == 0) {
        float best = -1e30f; int last = 0;
        for (int t2 = 0; t2 < 18; t2++) {
            float vv = sc[t2] + cend[t2];
            if (vv > best) { best = vv; last = t2; }
        }
        dec[255] = last;
        int tag = last;
        for (int s = 254; s >= 0; s--) { tag = hist[s][tag]; dec[s] = tag; }
        const int* yb = y + b * 256;
        float num = cstart[yb[0]] + emb[yb[0]];
        for (int s = 1; s < 256; s++) num += tr[yb[s-1] * 18 + yb[s]] + emb[s * 18 + yb[s]];
        num += cend[yb[255]];
        perb[b] = num - logZ;
    }
    __syncwarp();
    for (int s = j; s < 256; s += 32) dec_out[b * 256 + s] = (float)dec[s];
}

__global__ void loss_kernel(const float* __restrict__ perb, float* __restrict__ lossp) {
    if (threadIdx.x == 0) {
        float s = 0.0f;
        for (int b = 0; b < 32; b++) s += perb[b];
        *lossp = -s / 8192.0f;
    }
}

// ---------------- launch ----------------
#define LSTM_SMEM ((16384 + 4096) * 4)

extern "C" void kernel_launch(void* const* d_in, const int* in_sizes, int n_in,
                              void* d_out, int out_size) {
    (void)in_sizes; (void)n_in; (void)out_size;
    const int*   xw   = (const int*)d_in[0];
    const float* xpos = (const float*)d_in[1];
    const int*   xch  = (const int*)d_in[2];
    const float* xenr = (const float*)d_in[3];
    /* d_in[4] = mask (all ones, folded out) */
    const int*   yw   = (const int*)d_in[5];
    const float* wemb = (const float*)d_in[6];
    const float* cemb = (const float*)d_in[7];
    const float* cnnW = (const float*)d_in[8];
    const float* cnnb = (const float*)d_in[9];
    const float* lin1W = (const float*)d_in[10];
    const float* lin1b = (const float*)d_in[11];
    const float* lin2W = (const float*)d_in[12];
    const float* lin2b = (const float*)d_in[13];
    const float* cst  = (const float*)d_in[14];
    const float* cen  = (const float*)d_in[15];
    const float* ctr  = (const float*)d_in[16];
    const float* w0fI = (const float*)d_in[17];
    const float* w0fH = (const float*)d_in[18];
    const float* b0f  = (const float*)d_in[19];
    const float* w0bI = (const float*)d_in[20];
    const float* w0bH = (const float*)d_in[21];
    const float* b0b  = (const float*)d_in[22];
    const float* w1fI = (const float*)d_in[23];
    const float* w1fH = (const float*)d_in[24];
    const float* b1f  = (const float*)d_in[25];
    const float* w1bI = (const float*)d_in[26];
    const float* w1bH = (const float*)d_in[27];
    const float* b1b  = (const float*)d_in[28];
    float* out = (float*)d_out;

    cudaFuncSetAttribute(lstm_persistent, cudaFuncAttributeMaxDynamicSharedMemorySize, LSTM_SMEM);

    float *px, *pF, *pB, *po0, *po1, *ph1, *pperb;
    cudaGetSymbolAddress((void**)&px,    g_x);
    cudaGetSymbolAddress((void**)&pF,    g_preF);
    cudaGetSymbolAddress((void**)&pB,    g_preB);
    cudaGetSymbolAddress((void**)&po0,   g_out0);
    cudaGetSymbolAddress((void**)&po1,   g_out1);
    cudaGetSymbolAddress((void**)&ph1,   g_h1);
    cudaGetSymbolAddress((void**)&pperb, g_perb);
    __nv_bfloat16 *pwah, *pwal, *pwbh, *pwbl, *pxh, *pxl;
    cudaGetSymbolAddress((void**)&pwah, g_wah);
    cudaGetSymbolAddress((void**)&pwal, g_wal);
    cudaGetSymbolAddress((void**)&pwbh, g_wbh);
    cudaGetSymbolAddress((void**)&pwbl, g_wbl);
    cudaGetSymbolAddress((void**)&pxh,  g_xh);
    cudaGetSymbolAddress((void**)&pxl,  g_xl);

    embed_cnn_kernel<<<NS, 128>>>(xw, xpos, xch, xenr, wemb, cemb, cnnW, cnnb);

    // ---- layer0 input projections (K=331 -> Kp=352) ----
    cvt_w<<<dim3(2, 2048), 256>>>(w0fI, pwah, pwal, IN0, IN0P);
    cvt_w<<<dim3(2, 2048), 256>>>(w0bI, pwbh, pwbl, IN0, IN0P);
    cvt_x<<<dim3(32, IN0P), 256>>>(px, pxh, pxl, IN0);
    bgemm<<<dim3(64, 16, 2), 256>>>(pwah, pwal, b0f, pF, pwbh, pwbl, b0b, pB, NS, IN0P);
    lstm_reset<<<32, 1024>>>();
    lstm_persistent<<<128, 256, LSTM_SMEM>>>(pF, pB, w0fH, w0bH, po0);

    // ---- layer1 input projections (K=1024) ----
    cvt_w<<<dim3(4, 2048), 256>>>(w1fI, pwah, pwal, 1024, 1024);
    cvt_w<<<dim3(4, 2048), 256>>>(w1bI, pwbh, pwbl, 1024, 1024);
    cvt_x<<<dim3(32, 1024), 256>>>(po0, pxh, pxl, 1024);
    bgemm<<<dim3(64, 16, 2), 256>>>(pwah, pwal, b1f, pF, pwbh, pwbl, b1b, pB, NS, 1024);
    lstm_reset<<<32, 1024>>>();
    lstm_persistent<<<128, 256, LSTM_SMEM>>>(pF, pB, w1fH, w1bH, po1);

    // ---- heads ----
    cvt_w<<<dim3(4, 128), 256>>>(lin1W, pwah, pwal, 1024, 1024);
    cvt_x<<<dim3(32, 1024), 256>>>(po1, pxh, pxl, 1024);
    bgemm<<<dim3(64, 1, 1), 256>>>(pwah, pwal, lin1b, ph1, pwah, pwal, lin1b, ph1, NS, 1024);
    lin2_kernel<<<2048, 128>>>(ph1, lin2W, lin2b, out);

    // CRF: em at out[0..147456), decoded at out[147456..155648), loss at out[155648]
    crf_kernel<<<32, 32>>>(out, yw, cst, cen, ctr, out + 147456, pperb);
    loss_kernel<<<1, 32>>>(pperb, out + 147456 + 8192);
}

// round 12
// speedup vs baseline: 1.5263x; 1.2550x over previous
#include <cuda_runtime.h>
#include <cuda_bf16.h>
#include <math.h>
#include <stdint.h>

#define NS 8192          /* B*S = 32*256 */
#define IN0 331
#define IN0P 352         /* IN0 padded to 32 */

// ---------------- barrier primitives ----------------
__device__ __forceinline__ unsigned ld_acq(const unsigned* p) {
    unsigned v; asm volatile("ld.acquire.gpu.global.u32 %0, [%1];" : "=r"(v) : "l"(p) : "memory"); return v;
}
__device__ __forceinline__ void st_rel(unsigned* p, unsigned v) {
    asm volatile("st.release.gpu.global.u32 [%0], %1;" :: "l"(p), "r"(v) : "memory");
}

// ---------------- mma helpers ----------------
__device__ __forceinline__ uint32_t smem_u32(const void* p) {
    uint32_t a; asm("{ .reg .u64 t; cvta.to.shared.u64 t, %1; cvt.u32.u64 %0, t; }" : "=r"(a) : "l"(p));
    return a;
}
__device__ __forceinline__ void ldmA(uint32_t* a, uint32_t saddr) {
    asm volatile("ldmatrix.sync.aligned.m8n8.x4.shared.b16 {%0,%1,%2,%3}, [%4];"
        : "=r"(a[0]), "=r"(a[1]), "=r"(a[2]), "=r"(a[3]) : "r"(saddr));
}
__device__ __forceinline__ void ldmBT(uint32_t* b, uint32_t saddr) {
    asm volatile("ldmatrix.sync.aligned.m8n8.x2.trans.shared.b16 {%0,%1}, [%2];"
        : "=r"(b[0]), "=r"(b[1]) : "r"(saddr));
}
__device__ __forceinline__ void mma16816(float* c, const uint32_t* a, const uint32_t* b) {
    asm volatile("mma.sync.aligned.m16n8k16.row.col.f32.bf16.bf16.f32 "
        "{%0,%1,%2,%3}, {%4,%5,%6,%7}, {%8,%9}, {%0,%1,%2,%3};"
        : "+f"(c[0]), "+f"(c[1]), "+f"(c[2]), "+f"(c[3])
        : "r"(a[0]), "r"(a[1]), "r"(a[2]), "r"(a[3]), "r"(b[0]), "r"(b[1]));
}
__device__ __forceinline__ void st_cg_u16(unsigned short* p, unsigned short v) {
    asm volatile("st.global.cg.u16 [%0], %1;" :: "l"(p), "h"(v) : "memory");
}

// ---------------- static device scratch ----------------
__device__ float g_x[IN0 * NS];       // [k][m], m = s*32 + b
__device__ float g_preF[2048 * NS];   // [gate*512+h][m]
__device__ float g_preB[2048 * NS];
__device__ float g_out0[1024 * NS];   // [dir*512+h][m]
__device__ float g_out1[1024 * NS];
__device__ float g_h1[128 * NS];      // [k][m]
__device__ unsigned g_hbf[3 * 32768]; // bf16 h state: [buf][dir][part][k][b] ushorts (uint-backed)
__device__ float g_perb[32];
__device__ unsigned g_flag[128];      // [dir*64 + slot] step flags
// pre-split bf16 GEMM operands (padded K)
__device__ __nv_bfloat16 g_wah[2048 * 1024], g_wal[2048 * 1024];
__device__ __nv_bfloat16 g_wbh[2048 * 1024], g_wbl[2048 * 1024];
__device__ __nv_bfloat16 g_xh[1024 * NS],   g_xl[1024 * NS];

// ---------------- conversion kernels (fp32 -> bf16 hi/lo, padded) ----------------
__global__ void cvt_w(const float* __restrict__ src, __nv_bfloat16* __restrict__ hi,
                      __nv_bfloat16* __restrict__ lo, int K, int Kp) {
    int row = blockIdx.y;
    int k = blockIdx.x * 256 + threadIdx.x;
    if (k >= Kp) return;
    float v = (k < K) ? src[row * K + k] : 0.0f;
    __nv_bfloat16 h = __float2bfloat16(v);
    __nv_bfloat16 l = __float2bfloat16(v - __bfloat162float(h));
    hi[row * Kp + k] = h;
    lo[row * Kp + k] = l;
}
__global__ void cvt_x(const float* __restrict__ src, __nv_bfloat16* __restrict__ hi,
                      __nv_bfloat16* __restrict__ lo, int K) {
    int row = blockIdx.y;
    int col = blockIdx.x * 256 + threadIdx.x;
    float v = (row < K) ? src[row * NS + col] : 0.0f;
    __nv_bfloat16 h = __float2bfloat16(v);
    __nv_bfloat16 l = __float2bfloat16(v - __bfloat162float(h));
    hi[row * NS + col] = h;
    lo[row * NS + col] = l;
}

// ---------------- embeddings + char CNN + concat + relu (writes x^T [k][m]) ----------------
__global__ void embed_cnn_kernel(const int* __restrict__ xw, const float* __restrict__ xpos,
                                 const int* __restrict__ xch, const float* __restrict__ xenr,
                                 const float* __restrict__ wemb, const float* __restrict__ cemb,
                                 const float* __restrict__ cnnW, const float* __restrict__ cnnb) {
    int n = blockIdx.x;              // b*256+s
    int b = n >> 8, s = n & 255;
    int m = s * 32 + b;
    __shared__ float ce[16][124];
    __shared__ float convs[32][12];
    __shared__ float cpool[32];
    __shared__ int   ch[16];
    int tid = threadIdx.x;
    int lane = tid & 31, w = tid >> 5;
    if (tid < 16) ch[tid] = xch[n * 16 + tid];
    __syncthreads();
    for (int i = tid; i < 16 * 124; i += 128) {
        int p = i / 124, c = i % 124;
        ce[p][c] = cemb[ch[p] * 124 + c];
    }
    __syncthreads();

    for (int og = w; og < 8; og += 4) {
        float Wr[4][4][5];
        #pragma unroll
        for (int cc = 0; cc < 4; cc++) {
            int c = lane + 32 * cc;
            #pragma unroll
            for (int oo = 0; oo < 4; oo++)
                #pragma unroll
                for (int k = 0; k < 5; k++)
                    Wr[oo][cc][k] = (c < 124) ? cnnW[(og * 4 + oo) * 620 + c * 5 + k] : 0.0f;
        }
        float cw[4][5];
        #pragma unroll
        for (int cc = 0; cc < 4; cc++) {
            int c = lane + 32 * cc;
            #pragma unroll
            for (int k = 0; k < 5; k++)
                cw[cc][k] = (c < 124) ? ce[k][c] : 0.0f;
        }
        for (int p = 0; p < 12; p++) {
            float acc[4] = {0.0f, 0.0f, 0.0f, 0.0f};
            #pragma unroll
            for (int oo = 0; oo < 4; oo++)
                #pragma unroll
                for (int cc = 0; cc < 4; cc++)
                    #pragma unroll
                    for (int k = 0; k < 5; k++)
                        acc[oo] += Wr[oo][cc][k] * cw[cc][k];
            #pragma unroll
            for (int oo = 0; oo < 4; oo++) {
                #pragma unroll
                for (int off = 16; off; off >>= 1)
                    acc[oo] += __shfl_xor_sync(0xffffffffu, acc[oo], off);
                if (lane == 0) convs[og * 4 + oo][p] = acc[oo] + cnnb[og * 4 + oo];
            }
            if (p < 11) {
                #pragma unroll
                for (int cc = 0; cc < 4; cc++) {
                    int c = lane + 32 * cc;
                    #pragma unroll
                    for (int k = 0; k < 4; k++) cw[cc][k] = cw[cc][k + 1];
                    cw[cc][4] = (c < 124) ? ce[p + 5][c] : 0.0f;
                }
            }
        }
    }
    __syncthreads();
    if (tid < 32) {
        float mx = convs[tid][0];
        #pragma unroll
        for (int p = 1; p < 12; p++) mx = fmaxf(mx, convs[tid][p]);
        cpool[tid] = mx;
    }
    __syncthreads();
    int widx = xw[n];
    for (int j = tid; j < IN0; j += 128) {
        float v;
        if      (j < 256) v = wemb[widx * 256 + j];
        else if (j < 292) v = xpos[n * 36 + (j - 256)];
        else if (j < 324) v = cpool[j - 292];
        else              v = xenr[n * 7 + (j - 324)];
        g_x[j * NS + m] = fmaxf(v, 0.0f);
    }
}

// ---------------- split-bf16 tensor GEMM (pre-split operands, fused F/B via grid.z) ----------
__global__ __launch_bounds__(256) void bgemm(
    const __nv_bfloat16* __restrict__ WhA, const __nv_bfloat16* __restrict__ WlA,
    const float* __restrict__ biasA, float* __restrict__ CA,
    const __nv_bfloat16* __restrict__ WhB, const __nv_bfloat16* __restrict__ WlB,
    const float* __restrict__ biasB, float* __restrict__ CB,
    int J, int Kp
) {
    __shared__ __align__(16) unsigned short As[2][128 * 40];
    __shared__ __align__(16) unsigned short Bs[2][32 * 136];
    int tid = threadIdx.x, lane = tid & 31, wid = tid >> 5;
    int j0 = blockIdx.x * 128, i0 = blockIdx.y * 128;
    int wm = wid >> 2, wn = wid & 3;
    const __nv_bfloat16* Wh = blockIdx.z ? WhB : WhA;
    const __nv_bfloat16* Wl = blockIdx.z ? WlB : WlA;
    const float* bias = blockIdx.z ? biasB : biasA;
    float* C = blockIdx.z ? CB : CA;

    float acc[4][4][4];
    #pragma unroll
    for (int mt = 0; mt < 4; mt++)
        #pragma unroll
        for (int nt = 0; nt < 4; nt++)
            #pragma unroll
            for (int e = 0; e < 4; e++) acc[mt][nt][e] = 0.0f;

    uint32_t asb0 = smem_u32(As[0]), asb1 = smem_u32(As[1]);
    uint32_t bsb0 = smem_u32(Bs[0]), bsb1 = smem_u32(Bs[1]);

    int KB = Kp >> 5;
    for (int kb = 0; kb < KB; kb++) {
        int kb32 = kb << 5;
        #pragma unroll
        for (int it = 0; it < 2; it++) {
            int idx = it * 256 + tid;
            int row = idx >> 2, k8 = (idx & 3) << 3;
            size_t go = (size_t)(i0 + row) * Kp + kb32 + k8;
            *(uint4*)&As[0][row * 40 + k8] = *(const uint4*)(Wh + go);
            *(uint4*)&As[1][row * 40 + k8] = *(const uint4*)(Wl + go);
        }
        #pragma unroll
        for (int it = 0; it < 2; it++) {
            int idx = it * 256 + tid;
            int krow = idx >> 4, n8 = (idx & 15) << 3;
            size_t go = (size_t)(kb32 + krow) * J + j0 + n8;
            *(uint4*)&Bs[0][krow * 136 + n8] = *(const uint4*)(g_xh + go);
            *(uint4*)&Bs[1][krow * 136 + n8] = *(const uint4*)(g_xl + go);
        }
        __syncthreads();
        #pragma unroll
        for (int ks = 0; ks < 2; ks++) {
            uint32_t Ah[4][4], Al[4][4], Bh[4][2], Bl[4][2];
            #pragma unroll
            for (int mt = 0; mt < 4; mt++) {
                int row0 = wm * 64 + mt * 16;
                uint32_t off = (uint32_t)((row0 + (lane & 15)) * 40 + ks * 16 + ((lane >> 4) << 3)) * 2;
                ldmA(Ah[mt], asb0 + off);
                ldmA(Al[mt], asb1 + off);
            }
            #pragma unroll
            for (int nt = 0; nt < 4; nt++) {
                int n0 = wn * 32 + nt * 8;
                uint32_t off = (uint32_t)((ks * 16 + (lane & 15)) * 136 + n0) * 2;
                ldmBT(Bh[nt], bsb0 + off);
                ldmBT(Bl[nt], bsb1 + off);
            }
            #pragma unroll
            for (int mt = 0; mt < 4; mt++)
                #pragma unroll
                for (int nt = 0; nt < 4; nt++) {
                    mma16816(acc[mt][nt], Ah[mt], Bh[nt]);
                    mma16816(acc[mt][nt], Ah[mt], Bl[nt]);
                    mma16816(acc[mt][nt], Al[mt], Bh[nt]);
                }
        }
        __syncthreads();
    }
    int g = lane >> 2, q = lane & 3;
    #pragma unroll
    for (int mt = 0; mt < 4; mt++) {
        int r0 = i0 + wm * 64 + mt * 16 + g;
        float bv0 = __ldg(bias + r0), bv1 = __ldg(bias + r0 + 8);
        #pragma unroll
        for (int nt = 0; nt < 4; nt++) {
            int col = j0 + wn * 32 + nt * 8 + q * 2;
            float2 o0 = make_float2(acc[mt][nt][0] + bv0, acc[mt][nt][1] + bv0);
            float2 o1 = make_float2(acc[mt][nt][2] + bv1, acc[mt][nt][3] + bv1);
            *(float2*)&C[(size_t)r0 * J + col] = o0;
            *(float2*)&C[(size_t)(r0 + 8) * J + col] = o1;
        }
    }
}

// ---------------- LSTM reset: zero bf16 h buffer 0 + flags ----------------
__global__ void lstm_reset() {
    int idx = blockIdx.x * 1024 + threadIdx.x;
    if (idx < 32768) g_hbf[idx] = 0u;   // buf 0: 65536 ushorts (bf16 zero == 0x0000)
    if (idx < 128) g_flag[idx] = 0u;
}

// ---------------- persistent BiLSTM layer (tensor-core recurrence) ----------------
__device__ __forceinline__ float sigf(float x) { return 1.0f / (1.0f + expf(-x)); }

// smem layout (bytes): Whi[32][520]us @0 (33280), Wlo @33280, Hhi[512][40]us @66560 (40960),
// Hlo @107520, zb[8][32][34]f @148480 (34816) -> total 183296
#define LS_WHI 0
#define LS_WLO 33280
#define LS_HHI 66560
#define LS_HLO 107520
#define LS_ZB  148480
#define LSTM_SMEM 183296

__global__ __launch_bounds__(256, 1) void lstm_persistent(
    const float* __restrict__ preF, const float* __restrict__ preB,
    const float* __restrict__ whhF, const float* __restrict__ whhB,
    float* __restrict__ out
) {
    extern __shared__ __align__(16) char lsm[];
    unsigned short* sWhi = (unsigned short*)(lsm + LS_WHI);
    unsigned short* sWlo = (unsigned short*)(lsm + LS_WLO);
    unsigned short* sHhi = (unsigned short*)(lsm + LS_HHI);
    unsigned short* sHlo = (unsigned short*)(lsm + LS_HLO);
    float* zb = (float*)(lsm + LS_ZB);
    uint32_t bWhi = smem_u32(sWhi), bWlo = smem_u32(sWlo);
    uint32_t bHhi = smem_u32(sHhi), bHlo = smem_u32(sHlo);

    int tid = threadIdx.x;
    int lane = tid & 31, w = tid >> 5;
    int dir = blockIdx.x >> 6;
    int slot = blockIdx.x & 63;
    int h0 = slot * 8;
    const float* whh = dir ? whhB : whhF;
    const float* pre = dir ? preB : preF;
    unsigned* flg = &g_flag[dir * 64];
    unsigned short* hbf = (unsigned short*)g_hbf;

    // ---- stage + split weights once: 32 gate-rows (m = gate*8+hl) x 512 k ----
    for (int idx = tid; idx < 16384; idx += 256) {
        int m = idx >> 9, k = idx & 511;
        int grow = (m >> 3) * 512 + h0 + (m & 7);
        float v = whh[grow * 512 + k];
        __nv_bfloat16 bh = __float2bfloat16(v);
        __nv_bfloat16 bl = __float2bfloat16(v - __bfloat162float(bh));
        sWhi[m * 520 + k] = __bfloat16_as_ushort(bh);
        sWlo[m * 520 + k] = __bfloat16_as_ushort(bl);
    }
    float creg = 0.0f;
    int hl = tid >> 5, b = lane;

    float preg[4];
    {
        int t0 = dir ? 255 : 0;
        int m0 = t0 * 32 + b;
        #pragma unroll
        for (int g = 0; g < 4; g++) preg[g] = __ldg(&pre[(g * 512 + h0 + hl) * NS + m0]);
    }
    __syncthreads();

    int buf = 0;
    for (int step = 0; step < 256; step++) {
        int nbuf = buf + 1; if (nbuf == 3) nbuf = 0;
        const unsigned short* hsrc = hbf + buf * 65536 + dir * 32768;

        // ---- stage h hi/lo into ldmatrix-friendly smem (uint4 copies) ----
        #pragma unroll
        for (int l = 0; l < 8; l++) {
            int i = l * 256 + tid;           // 2048 uint4 per part
            int k = i >> 2, b8 = (i & 3) << 3;
            uint4 v0 = __ldcg((const uint4*)hsrc + i);
            *(uint4*)(sHhi + k * 40 + b8) = v0;
            uint4 v1 = __ldcg((const uint4*)(hsrc + 16384) + i);
            *(uint4*)(sHlo + k * 40 + b8) = v1;
        }
        __syncthreads();

        // ---- tensor-core recurrence: warp w = 64-k slice, all 32 gate-rows ----
        float acc[2][4][4];
        #pragma unroll
        for (int mt = 0; mt < 2; mt++)
            #pragma unroll
            for (int nt = 0; nt < 4; nt++)
                #pragma unroll
                for (int e = 0; e < 4; e++) acc[mt][nt][e] = 0.0f;

        #pragma unroll
        for (int kt = 0; kt < 4; kt++) {
            int kbase = w * 64 + kt * 16;
            uint32_t Ah[2][4], Al[2][4], Bh[4][2], Bl[4][2];
            #pragma unroll
            for (int mt = 0; mt < 2; mt++) {
                uint32_t off = (uint32_t)((mt * 16 + (lane & 15)) * 520 + kbase + ((lane >> 4) << 3)) * 2;
                ldmA(Ah[mt], bWhi + off);
                ldmA(Al[mt], bWlo + off);
            }
            #pragma unroll
            for (int nt = 0; nt < 4; nt++) {
                uint32_t off = (uint32_t)((kbase + (lane & 15)) * 40 + nt * 8) * 2;
                ldmBT(Bh[nt], bHhi + off);
                ldmBT(Bl[nt], bHlo + off);
            }
            #pragma unroll
            for (int mt = 0; mt < 2; mt++)
                #pragma unroll
                for (int nt = 0; nt < 4; nt++) {
                    mma16816(acc[mt][nt], Ah[mt], Bh[nt]);
                    mma16816(acc[mt][nt], Ah[mt], Bl[nt]);
                    mma16816(acc[mt][nt], Al[mt], Bh[nt]);
                }
        }
        // ---- write k-slice partials (padded rows: stride 34) ----
        {
            int g8 = lane >> 2, q = lane & 3;
            #pragma unroll
            for (int mt = 0; mt < 2; mt++)
                #pragma unroll
                for (int nt = 0; nt < 4; nt++) {
                    int m0 = mt * 16 + g8, n0 = nt * 8 + q * 2;
                    *(float2*)&zb[(w * 32 + m0) * 34 + n0] =
                        make_float2(acc[mt][nt][0], acc[mt][nt][1]);
                    *(float2*)&zb[(w * 32 + m0 + 8) * 34 + n0] =
                        make_float2(acc[mt][nt][2], acc[mt][nt][3]);
                }
        }
        __syncthreads();

        // ---- epilogue: thread = (hl, b) ----
        int t = dir ? 255 - step : step;
        int m = t * 32 + b;
        float z[4];
        #pragma unroll
        for (int g = 0; g < 4; g++) {
            int r = g * 8 + hl;
            float s = 0.0f;
            #pragma unroll
            for (int sl = 0; sl < 8; sl++) s += zb[(sl * 32 + r) * 34 + b];
            z[g] = s + preg[g];
        }
        float c = sigf(z[1]) * creg + sigf(z[0]) * tanhf(z[2]);
        float hn = sigf(z[3]) * tanhf(c);
        creg = c;
        int h = h0 + hl;
        {
            __nv_bfloat16 bh = __float2bfloat16(hn);
            __nv_bfloat16 bl = __float2bfloat16(hn - __bfloat162float(bh));
            unsigned short* hdst = hbf + nbuf * 65536 + dir * 32768;
            st_cg_u16(hdst + h * 32 + b, __bfloat16_as_ushort(bh));
            st_cg_u16(hdst + 16384 + h * 32 + b, __bfloat16_as_ushort(bl));
        }
        __syncthreads();             // all h stores done before arrive

        if (tid == 0 && step < 255) st_rel(&flg[slot], (unsigned)(step + 1));

        out[(dir * 512 + h) * NS + m] = hn;
        {
            int tn = dir ? 255 - (step + 1) : (step + 1);
            if (step == 255) tn = t;
            int mn = tn * 32 + b;
            #pragma unroll
            for (int g = 0; g < 4; g++) preg[g] = __ldg(&pre[(g * 512 + h0 + hl) * NS + mn]);
        }
        if (step < 255) {
            if (tid < 32) {
                unsigned target = (unsigned)(step + 1);
                for (;;) {
                    unsigned v0 = ld_acq(&flg[tid]);
                    unsigned v1 = ld_acq(&flg[32 + tid]);
                    if (__all_sync(0xffffffffu, (v0 >= target) && (v1 >= target))) break;
                }
            }
            __syncthreads();
        }
        buf = nbuf;
    }
}

// ---------------- lin2: 4 m per block, transposed W in smem ----------------
__global__ void lin2_kernel(const float* __restrict__ h1, const float* __restrict__ W,
                            const float* __restrict__ bias, float* __restrict__ em) {
    __shared__ float Wt[128 * 18];
    __shared__ float rows[4][128];
    int tid = threadIdx.x, lane = tid & 31, w = tid >> 5;
    for (int idx = tid; idx < 2304; idx += 128) {
        int o = idx >> 7, k = idx & 127;
        Wt[k * 18 + o] = W[idx];
    }
    int mm = blockIdx.x * 4 + w;
    for (int i = lane; i < 128; i += 32) rows[w][i] = h1[i * NS + mm];
    __syncthreads();
    if (lane < 18) {
        float acc = bias[lane];
        #pragma unroll 8
        for (int k = 0; k < 128; k++) acc += rows[w][k] * Wt[k * 18 + lane];
        int s = mm >> 5, b = mm & 31;
        em[(b * 256 + s) * 18 + lane] = acc;
    }
}

// ---------------- CRF ----------------
__global__ void crf_kernel(const float* __restrict__ em, const int* __restrict__ y,
                           const float* __restrict__ cstart, const float* __restrict__ cend,
                           const float* __restrict__ ctrans,
                           float* __restrict__ dec_out, float* __restrict__ perb) {
    __shared__ float tr[324];
    __shared__ float sc[18], fs[18];
    __shared__ int hist[255][18];
    __shared__ int dec[256];
    int b = blockIdx.x, j = threadIdx.x;
    for (int i = j; i < 324; i += 32) tr[i] = ctrans[i];
    const float* emb = em + b * 256 * 18;
    if (j < 18) { float v = cstart[j] + emb[j]; sc[j] = v; fs[j] = v; }
    __syncwarp();
    for (int s = 1; s < 256; s++) {
        float bestv = -1e30f, m = -1e30f, e = 0.0f, ssum = 0.0f;
        int bi = 0;
        if (j < 18) {
            e = emb[s * 18 + j];
            #pragma unroll
            for (int i = 0; i < 18; i++) {
                float t1 = sc[i] + tr[i * 18 + j];
                if (t1 > bestv) { bestv = t1; bi = i; }
                float t2 = fs[i] + tr[i * 18 + j];
                m = fmaxf(m, t2);
            }
            #pragma unroll
            for (int i = 0; i < 18; i++) ssum += __expf(fs[i] + tr[i * 18 + j] - m);
        }
        __syncwarp();
        if (j < 18) {
            sc[j] = bestv + e;
            fs[j] = m + __logf(ssum) + e;
            hist[s - 1][j] = bi;
        }
        __syncwarp();
    }
    float v = (j < 18) ? fs[j] + cend[j] : -1e30f;
    float m = v;
    for (int o = 16; o; o >>= 1) m = fmaxf(m, __shfl_xor_sync(0xffffffffu, m, o));
    float ex = (j < 18) ? __expf(v - m) : 0.0f;
    for (int o = 16; o; o >>= 1) ex += __shfl_xor_sync(0xffffffffu, ex, o);
    float logZ = m + __logf(ex);

    if (j == 0) {
        float best = -1e30f; int last = 0;
        for (int t2 = 0; t2 < 18; t2++) {
            float vv = sc[t2] + cend[t2];
            if (vv > best) { best = vv; last = t2; }
        }
        dec[255] = last;
        int tag = last;
        for (int s = 254; s >= 0; s--) { tag = hist[s][tag]; dec[s] = tag; }
        const int* yb = y + b * 256;
        float num = cstart[yb[0]] + emb[yb[0]];
        for (int s = 1; s < 256; s++) num += tr[yb[s-1] * 18 + yb[s]] + emb[s * 18 + yb[s]];
        num += cend[yb[255]];
        perb[b] = num - logZ;
    }
    __syncwarp();
    for (int s = j; s < 256; s += 32) dec_out[b * 256 + s] = (float)dec[s];
}

__global__ void loss_kernel(const float* __restrict__ perb, float* __restrict__ lossp) {
    if (threadIdx.x == 0) {
        float s = 0.0f;
        for (int b = 0; b < 32; b++) s += perb[b];
        *lossp = -s / 8192.0f;
    }
}

// ---------------- launch ----------------
extern "C" void kernel_launch(void* const* d_in, const int* in_sizes, int n_in,
                              void* d_out, int out_size) {
    (void)in_sizes; (void)n_in; (void)out_size;
    const int*   xw   = (const int*)d_in[0];
    const float* xpos = (const float*)d_in[1];
    const int*   xch  = (const int*)d_in[2];
    const float* xenr = (const float*)d_in[3];
    /* d_in[4] = mask (all ones, folded out) */
    const int*   yw   = (const int*)d_in[5];
    const float* wemb = (const float*)d_in[6];
    const float* cemb = (const float*)d_in[7];
    const float* cnnW = (const float*)d_in[8];
    const float* cnnb = (const float*)d_in[9];
    const float* lin1W = (const float*)d_in[10];
    const float* lin1b = (const float*)d_in[11];
    const float* lin2W = (const float*)d_in[12];
    const float* lin2b = (const float*)d_in[13];
    const float* cst  = (const float*)d_in[14];
    const float* cen  = (const float*)d_in[15];
    const float* ctr  = (const float*)d_in[16];
    const float* w0fI = (const float*)d_in[17];
    const float* w0fH = (const float*)d_in[18];
    const float* b0f  = (const float*)d_in[19];
    const float* w0bI = (const float*)d_in[20];
    const float* w0bH = (const float*)d_in[21];
    const float* b0b  = (const float*)d_in[22];
    const float* w1fI = (const float*)d_in[23];
    const float* w1fH = (const float*)d_in[24];
    const float* b1f  = (const float*)d_in[25];
    const float* w1bI = (const float*)d_in[26];
    const float* w1bH = (const float*)d_in[27];
    const float* b1b  = (const float*)d_in[28];
    float* out = (float*)d_out;

    cudaFuncSetAttribute(lstm_persistent, cudaFuncAttributeMaxDynamicSharedMemorySize, LSTM_SMEM);

    float *px, *pF, *pB, *po0, *po1, *ph1, *pperb;
    cudaGetSymbolAddress((void**)&px,    g_x);
    cudaGetSymbolAddress((void**)&pF,    g_preF);
    cudaGetSymbolAddress((void**)&pB,    g_preB);
    cudaGetSymbolAddress((void**)&po0,   g_out0);
    cudaGetSymbolAddress((void**)&po1,   g_out1);
    cudaGetSymbolAddress((void**)&ph1,   g_h1);
    cudaGetSymbolAddress((void**)&pperb, g_perb);
    __nv_bfloat16 *pwah, *pwal, *pwbh, *pwbl, *pxh, *pxl;
    cudaGetSymbolAddress((void**)&pwah, g_wah);
    cudaGetSymbolAddress((void**)&pwal, g_wal);
    cudaGetSymbolAddress((void**)&pwbh, g_wbh);
    cudaGetSymbolAddress((void**)&pwbl, g_wbl);
    cudaGetSymbolAddress((void**)&pxh,  g_xh);
    cudaGetSymbolAddress((void**)&pxl,  g_xl);

    embed_cnn_kernel<<<NS, 128>>>(xw, xpos, xch, xenr, wemb, cemb, cnnW, cnnb);

    // ---- layer0 input projections (K=331 -> Kp=352) ----
    cvt_w<<<dim3(2, 2048), 256>>>(w0fI, pwah, pwal, IN0, IN0P);
    cvt_w<<<dim3(2, 2048), 256>>>(w0bI, pwbh, pwbl, IN0, IN0P);
    cvt_x<<<dim3(32, IN0P), 256>>>(px, pxh, pxl, IN0);
    bgemm<<<dim3(64, 16, 2), 256>>>(pwah, pwal, b0f, pF, pwbh, pwbl, b0b, pB, NS, IN0P);
    lstm_reset<<<32, 1024>>>();
    lstm_persistent<<<128, 256, LSTM_SMEM>>>(pF, pB, w0fH, w0bH, po0);

    // ---- layer1 input projections (K=1024) ----
    cvt_w<<<dim3(4, 2048), 256>>>(w1fI, pwah, pwal, 1024, 1024);
    cvt_w<<<dim3(4, 2048), 256>>>(w1bI, pwbh, pwbl, 1024, 1024);
    cvt_x<<<dim3(32, 1024), 256>>>(po0, pxh, pxl, 1024);
    bgemm<<<dim3(64, 16, 2), 256>>>(pwah, pwal, b1f, pF, pwbh, pwbl, b1b, pB, NS, 1024);
    lstm_reset<<<32, 1024>>>();
    lstm_persistent<<<128, 256, LSTM_SMEM>>>(pF, pB, w1fH, w1bH, po1);

    // ---- heads ----
    cvt_w<<<dim3(4, 128), 256>>>(lin1W, pwah, pwal, 1024, 1024);
    cvt_x<<<dim3(32, 1024), 256>>>(po1, pxh, pxl, 1024);
    bgemm<<<dim3(64, 1, 1), 256>>>(pwah, pwal, lin1b, ph1, pwah, pwal, lin1b, ph1, NS, 1024);
    lin2_kernel<<<2048, 128>>>(ph1, lin2W, lin2b, out);

    // CRF: em at out[0..147456), decoded at out[147456..155648), loss at out[155648]
    crf_kernel<<<32, 32>>>(out, yw, cst, cen, ctr, out + 147456, pperb);
    loss_kernel<<<1, 32>>>(pperb, out + 147456 + 8192);
}

// round 14
// speedup vs baseline: 1.7794x; 1.1658x over previous
#include <cuda_runtime.h>
#include <cuda_bf16.h>
#include <math.h>
#include <stdint.h>

#define NS 8192          /* B*S = 32*256 */
#define IN0 331
#define IN0P 352         /* IN0 padded to 32 */

// ---------------- barrier primitives ----------------
__device__ __forceinline__ unsigned ld_acq(const unsigned* p) {
    unsigned v; asm volatile("ld.acquire.gpu.global.u32 %0, [%1];" : "=r"(v) : "l"(p) : "memory"); return v;
}
__device__ __forceinline__ void st_rel(unsigned* p, unsigned v) {
    asm volatile("st.release.gpu.global.u32 [%0], %1;" :: "l"(p), "r"(v) : "memory");
}

// ---------------- mma / async helpers ----------------
__device__ __forceinline__ uint32_t smem_u32(const void* p) {
    uint32_t a; asm("{ .reg .u64 t; cvta.to.shared.u64 t, %1; cvt.u32.u64 %0, t; }" : "=r"(a) : "l"(p));
    return a;
}
__device__ __forceinline__ void ldmA(uint32_t* a, uint32_t saddr) {
    asm volatile("ldmatrix.sync.aligned.m8n8.x4.shared.b16 {%0,%1,%2,%3}, [%4];"
        : "=r"(a[0]), "=r"(a[1]), "=r"(a[2]), "=r"(a[3]) : "r"(saddr));
}
__device__ __forceinline__ void ldmBT(uint32_t* b, uint32_t saddr) {
    asm volatile("ldmatrix.sync.aligned.m8n8.x2.trans.shared.b16 {%0,%1}, [%2];"
        : "=r"(b[0]), "=r"(b[1]) : "r"(saddr));
}
__device__ __forceinline__ void mma16816(float* c, const uint32_t* a, const uint32_t* b) {
    asm volatile("mma.sync.aligned.m16n8k16.row.col.f32.bf16.bf16.f32 "
        "{%0,%1,%2,%3}, {%4,%5,%6,%7}, {%8,%9}, {%0,%1,%2,%3};"
        : "+f"(c[0]), "+f"(c[1]), "+f"(c[2]), "+f"(c[3])
        : "r"(a[0]), "r"(a[1]), "r"(a[2]), "r"(a[3]), "r"(b[0]), "r"(b[1]));
}
__device__ __forceinline__ void st_cg_u16(unsigned short* p, unsigned short v) {
    asm volatile("st.global.cg.u16 [%0], %1;" :: "l"(p), "h"(v) : "memory");
}
__device__ __forceinline__ void cpa16(uint32_t s, const void* g) {
    asm volatile("cp.async.cg.shared.global [%0], [%1], 16;" :: "r"(s), "l"(g) : "memory");
}
#define CPA_COMMIT() asm volatile("cp.async.commit_group;" ::: "memory")
#define CPA_WAIT0()  asm volatile("cp.async.wait_group 0;" ::: "memory")
#define CPA_WAIT1()  asm volatile("cp.async.wait_group 1;" ::: "memory")

// ---------------- static device scratch ----------------
__device__ float g_preF[2048 * NS];   // [gate*512+h][m]
__device__ float g_preB[2048 * NS];
__device__ float g_h1[128 * NS];      // [k][m]
__device__ unsigned g_hbf[3 * 32768]; // bf16 h state: [buf][dir][part][k][b] ushorts
__device__ float g_perb[32];
__device__ unsigned g_flag[128];      // [dir*64 + slot] step flags
// pre-split bf16 GEMM operands (padded K)
__device__ __nv_bfloat16 g_wah[2048 * 1024], g_wal[2048 * 1024];
__device__ __nv_bfloat16 g_wbh[2048 * 1024], g_wbl[2048 * 1024];
__device__ __nv_bfloat16 g_xh[1024 * NS],   g_xl[1024 * NS];

// ---------------- conversion: fp32 -> bf16 hi/lo (weights, padded) ----------------
__global__ void cvt_w(const float* __restrict__ src, __nv_bfloat16* __restrict__ hi,
                      __nv_bfloat16* __restrict__ lo, int K, int Kp) {
    int row = blockIdx.y;
    int k = blockIdx.x * 256 + threadIdx.x;
    if (k >= Kp) return;
    float v = (k < K) ? src[row * K + k] : 0.0f;
    __nv_bfloat16 h = __float2bfloat16(v);
    __nv_bfloat16 l = __float2bfloat16(v - __bfloat162float(h));
    hi[row * Kp + k] = h;
    lo[row * Kp + k] = l;
}
// zero pad rows [IN0, IN0P) of g_xh/g_xl
__global__ void pad_x() {
    int idx = blockIdx.x * 256 + threadIdx.x;   // 21*8192 = 172032
    if (idx < (IN0P - IN0) * NS) {
        g_xh[IN0 * NS + idx] = __float2bfloat16(0.0f);
        g_xl[IN0 * NS + idx] = __float2bfloat16(0.0f);
    }
}

// ---------------- embeddings + char CNN + concat + relu (writes split-bf16 x) ------------
__global__ void embed_cnn_kernel(const int* __restrict__ xw, const float* __restrict__ xpos,
                                 const int* __restrict__ xch, const float* __restrict__ xenr,
                                 const float* __restrict__ wemb, const float* __restrict__ cemb,
                                 const float* __restrict__ cnnW, const float* __restrict__ cnnb) {
    int n = blockIdx.x;              // b*256+s
    int b = n >> 8, s = n & 255;
    int m = s * 32 + b;
    __shared__ float ce[16][124];
    __shared__ float convs[32][12];
    __shared__ float cpool[32];
    __shared__ int   ch[16];
    int tid = threadIdx.x;
    int lane = tid & 31, w = tid >> 5;
    if (tid < 16) ch[tid] = xch[n * 16 + tid];
    __syncthreads();
    for (int i = tid; i < 16 * 124; i += 128) {
        int p = i / 124, c = i % 124;
        ce[p][c] = cemb[ch[p] * 124 + c];
    }
    __syncthreads();

    for (int og = w; og < 8; og += 4) {
        float Wr[4][4][5];
        #pragma unroll
        for (int cc = 0; cc < 4; cc++) {
            int c = lane + 32 * cc;
            #pragma unroll
            for (int oo = 0; oo < 4; oo++)
                #pragma unroll
                for (int k = 0; k < 5; k++)
                    Wr[oo][cc][k] = (c < 124) ? cnnW[(og * 4 + oo) * 620 + c * 5 + k] : 0.0f;
        }
        float cw[4][5];
        #pragma unroll
        for (int cc = 0; cc < 4; cc++) {
            int c = lane + 32 * cc;
            #pragma unroll
            for (int k = 0; k < 5; k++)
                cw[cc][k] = (c < 124) ? ce[k][c] : 0.0f;
        }
        for (int p = 0; p < 12; p++) {
            float acc[4] = {0.0f, 0.0f, 0.0f, 0.0f};
            #pragma unroll
            for (int oo = 0; oo < 4; oo++)
                #pragma unroll
                for (int cc = 0; cc < 4; cc++)
                    #pragma unroll
                    for (int k = 0; k < 5; k++)
                        acc[oo] += Wr[oo][cc][k] * cw[cc][k];
            #pragma unroll
            for (int oo = 0; oo < 4; oo++) {
                #pragma unroll
                for (int off = 16; off; off >>= 1)
                    acc[oo] += __shfl_xor_sync(0xffffffffu, acc[oo], off);
                if (lane == 0) convs[og * 4 + oo][p] = acc[oo] + cnnb[og * 4 + oo];
            }
            if (p < 11) {
                #pragma unroll
                for (int cc = 0; cc < 4; cc++) {
                    int c = lane + 32 * cc;
                    #pragma unroll
                    for (int k = 0; k < 4; k++) cw[cc][k] = cw[cc][k + 1];
                    cw[cc][4] = (c < 124) ? ce[p + 5][c] : 0.0f;
                }
            }
        }
    }
    __syncthreads();
    if (tid < 32) {
        float mx = convs[tid][0];
        #pragma unroll
        for (int p = 1; p < 12; p++) mx = fmaxf(mx, convs[tid][p]);
        cpool[tid] = mx;
    }
    __syncthreads();
    int widx = xw[n];
    for (int j = tid; j < IN0; j += 128) {
        float v;
        if      (j < 256) v = wemb[widx * 256 + j];
        else if (j < 292) v = xpos[n * 36 + (j - 256)];
        else if (j < 324) v = cpool[j - 292];
        else              v = xenr[n * 7 + (j - 324)];
        v = fmaxf(v, 0.0f);
        __nv_bfloat16 bh = __float2bfloat16(v);
        __nv_bfloat16 bl = __float2bfloat16(v - __bfloat162float(bh));
        g_xh[j * NS + m] = bh;
        g_xl[j * NS + m] = bl;
    }
}

// ---------------- split-bf16 tensor GEMM (cp.async double-buffered, fused F/B) ----------
// smem per stage: Ahi(10240) Alo(10240) Bhi(8704) Blo(8704) = 37888; x2 stages
#define GST 37888
#define GEMM_SMEM (2 * GST)

__global__ __launch_bounds__(256) void bgemm(
    const __nv_bfloat16* __restrict__ WhA, const __nv_bfloat16* __restrict__ WlA,
    const float* __restrict__ biasA, float* __restrict__ CA,
    const __nv_bfloat16* __restrict__ WhB, const __nv_bfloat16* __restrict__ WlB,
    const float* __restrict__ biasB, float* __restrict__ CB,
    int J, int Kp
) {
    extern __shared__ __align__(16) char gsm[];
    uint32_t sb = smem_u32(gsm);
    int tid = threadIdx.x, lane = tid & 31, wid = tid >> 5;
    int j0 = blockIdx.x * 128, i0 = blockIdx.y * 128;
    int wm = wid >> 2, wn = wid & 3;
    const __nv_bfloat16* Wh = blockIdx.z ? WhB : WhA;
    const __nv_bfloat16* Wl = blockIdx.z ? WlB : WlA;
    const float* bias = blockIdx.z ? biasB : biasA;
    float* C = blockIdx.z ? CB : CA;

    float acc[4][4][4];
    #pragma unroll
    for (int mt = 0; mt < 4; mt++)
        #pragma unroll
        for (int nt = 0; nt < 4; nt++)
            #pragma unroll
            for (int e = 0; e < 4; e++) acc[mt][nt][e] = 0.0f;

    int KB = Kp >> 5;

    auto issue = [&](int kb, int bi) {
        uint32_t base = sb + (uint32_t)bi * GST;
        int kb32 = kb << 5;
        #pragma unroll
        for (int it = 0; it < 2; it++) {
            int idx = it * 256 + tid;
            int row = idx >> 2, k8 = (idx & 3) << 3;
            size_t go = (size_t)(i0 + row) * Kp + kb32 + k8;
            cpa16(base + (uint32_t)(row * 40 + k8) * 2, Wh + go);
            cpa16(base + 10240u + (uint32_t)(row * 40 + k8) * 2, Wl + go);
            int krow = idx >> 4, n8 = (idx & 15) << 3;
            size_t go2 = (size_t)(kb32 + krow) * J + j0 + n8;
            cpa16(base + 20480u + (uint32_t)(krow * 136 + n8) * 2, g_xh + go2);
            cpa16(base + 29184u + (uint32_t)(krow * 136 + n8) * 2, g_xl + go2);
        }
        CPA_COMMIT();
    };

    issue(0, 0);
    for (int kb = 0; kb < KB; kb++) {
        int bi = kb & 1;
        if (kb + 1 < KB) { issue(kb + 1, bi ^ 1); CPA_WAIT1(); }
        else             { CPA_WAIT0(); }
        __syncthreads();
        uint32_t ab = sb + (uint32_t)bi * GST;
        uint32_t ah = ab, al = ab + 10240u, bh = ab + 20480u, bl = ab + 29184u;
        #pragma unroll
        for (int ks = 0; ks < 2; ks++) {
            uint32_t Ah[4][4], Al[4][4], Bh[4][2], Bl[4][2];
            #pragma unroll
            for (int mt = 0; mt < 4; mt++) {
                int row0 = wm * 64 + mt * 16;
                uint32_t off = (uint32_t)((row0 + (lane & 15)) * 40 + ks * 16 + ((lane >> 4) << 3)) * 2;
                ldmA(Ah[mt], ah + off);
                ldmA(Al[mt], al + off);
            }
            #pragma unroll
            for (int nt = 0; nt < 4; nt++) {
                int n0 = wn * 32 + nt * 8;
                uint32_t off = (uint32_t)((ks * 16 + (lane & 15)) * 136 + n0) * 2;
                ldmBT(Bh[nt], bh + off);
                ldmBT(Bl[nt], bl + off);
            }
            #pragma unroll
            for (int mt = 0; mt < 4; mt++)
                #pragma unroll
                for (int nt = 0; nt < 4; nt++) {
                    mma16816(acc[mt][nt], Ah[mt], Bh[nt]);
                    mma16816(acc[mt][nt], Ah[mt], Bl[nt]);
                    mma16816(acc[mt][nt], Al[mt], Bh[nt]);
                }
        }
        __syncthreads();
    }
    int g = lane >> 2, q = lane & 3;
    #pragma unroll
    for (int mt = 0; mt < 4; mt++) {
        int r0 = i0 + wm * 64 + mt * 16 + g;
        float bv0 = __ldg(bias + r0), bv1 = __ldg(bias + r0 + 8);
        #pragma unroll
        for (int nt = 0; nt < 4; nt++) {
            int col = j0 + wn * 32 + nt * 8 + q * 2;
            float2 o0 = make_float2(acc[mt][nt][0] + bv0, acc[mt][nt][1] + bv0);
            float2 o1 = make_float2(acc[mt][nt][2] + bv1, acc[mt][nt][3] + bv1);
            *(float2*)&C[(size_t)r0 * J + col] = o0;
            *(float2*)&C[(size_t)(r0 + 8) * J + col] = o1;
        }
    }
}

// ---------------- LSTM reset: zero bf16 h buffer 0 + flags ----------------
__global__ void lstm_reset() {
    int idx = blockIdx.x * 1024 + threadIdx.x;
    if (idx < 32768) g_hbf[idx] = 0u;
    if (idx < 128) g_flag[idx] = 0u;
}

// ---------------- persistent BiLSTM layer (tensor-core recurrence) ----------------
__device__ __forceinline__ float sigf(float x) { return 1.0f / (1.0f + expf(-x)); }

#define LS_WHI 0
#define LS_WLO 33280
#define LS_HHI 66560
#define LS_HLO 107520
#define LS_ZB  148480
#define LSTM_SMEM 183296

__global__ __launch_bounds__(256, 1) void lstm_persistent(
    const float* __restrict__ preF, const float* __restrict__ preB,
    const float* __restrict__ whhF, const float* __restrict__ whhB,
    __nv_bfloat16* __restrict__ outh, __nv_bfloat16* __restrict__ outl
) {
    extern __shared__ __align__(16) char lsm[];
    unsigned short* sWhi = (unsigned short*)(lsm + LS_WHI);
    unsigned short* sWlo = (unsigned short*)(lsm + LS_WLO);
    float* zb = (float*)(lsm + LS_ZB);
    uint32_t bWhi = smem_u32(lsm + LS_WHI), bWlo = smem_u32(lsm + LS_WLO);
    uint32_t bHhi = smem_u32(lsm + LS_HHI), bHlo = smem_u32(lsm + LS_HLO);

    int tid = threadIdx.x;
    int lane = tid & 31, w = tid >> 5;
    int dir = blockIdx.x >> 6;
    int slot = blockIdx.x & 63;
    int h0 = slot * 8;
    const float* whh = dir ? whhB : whhF;
    const float* pre = dir ? preB : preF;
    unsigned* flg = &g_flag[dir * 64];
    unsigned short* hbf = (unsigned short*)g_hbf;

    // ---- stage + split weights once ----
    for (int idx = tid; idx < 16384; idx += 256) {
        int m = idx >> 9, k = idx & 511;
        int grow = (m >> 3) * 512 + h0 + (m & 7);
        float v = whh[grow * 512 + k];
        __nv_bfloat16 bh = __float2bfloat16(v);
        __nv_bfloat16 bl = __float2bfloat16(v - __bfloat162float(bh));
        sWhi[m * 520 + k] = __bfloat16_as_ushort(bh);
        sWlo[m * 520 + k] = __bfloat16_as_ushort(bl);
    }
    float creg = 0.0f;
    int hl = tid >> 5, b = lane;

    float preg[4];
    {
        int t0 = dir ? 255 : 0;
        int m0 = t0 * 32 + b;
        #pragma unroll
        for (int g = 0; g < 4; g++) preg[g] = __ldg(&pre[(g * 512 + h0 + hl) * NS + m0]);
    }
    __syncthreads();

    int buf = 0;
    for (int step = 0; step < 256; step++) {
        int nbuf = buf + 1; if (nbuf == 3) nbuf = 0;
        const unsigned short* hsrc = hbf + buf * 65536 + dir * 32768;

        // ---- stage h hi/lo via cp.async ----
        #pragma unroll
        for (int l = 0; l < 8; l++) {
            int i = l * 256 + tid;           // 2048 uint4 per part
            int k = i >> 2, b8 = (i & 3) << 3;
            cpa16(bHhi + (uint32_t)(k * 40 + b8) * 2, (const char*)hsrc + (size_t)i * 16);
            cpa16(bHlo + (uint32_t)(k * 40 + b8) * 2, (const char*)(hsrc + 16384) + (size_t)i * 16);
        }
        CPA_COMMIT();
        CPA_WAIT0();
        __syncthreads();

        // ---- tensor-core recurrence: warp w = 64-k slice, all 32 gate-rows ----
        float acc[2][4][4];
        #pragma unroll
        for (int mt = 0; mt < 2; mt++)
            #pragma unroll
            for (int nt = 0; nt < 4; nt++)
                #pragma unroll
                for (int e = 0; e < 4; e++) acc[mt][nt][e] = 0.0f;

        #pragma unroll
        for (int kt = 0; kt < 4; kt++) {
            int kbase = w * 64 + kt * 16;
            uint32_t Ah[2][4], Al[2][4], Bh[4][2], Bl[4][2];
            #pragma unroll
            for (int mt = 0; mt < 2; mt++) {
                uint32_t off = (uint32_t)((mt * 16 + (lane & 15)) * 520 + kbase + ((lane >> 4) << 3)) * 2;
                ldmA(Ah[mt], bWhi + off);
                ldmA(Al[mt], bWlo + off);
            }
            #pragma unroll
            for (int nt = 0; nt < 4; nt++) {
                uint32_t off = (uint32_t)((kbase + (lane & 15)) * 40 + nt * 8) * 2;
                ldmBT(Bh[nt], bHhi + off);
                ldmBT(Bl[nt], bHlo + off);
            }
            #pragma unroll
            for (int mt = 0; mt < 2; mt++)
                #pragma unroll
                for (int nt = 0; nt < 4; nt++) {
                    mma16816(acc[mt][nt], Ah[mt], Bh[nt]);
                    mma16816(acc[mt][nt], Ah[mt], Bl[nt]);
                    mma16816(acc[mt][nt], Al[mt], Bh[nt]);
                }
        }
        // ---- write k-slice partials (stride 34) ----
        {
            int g8 = lane >> 2, q = lane & 3;
            #pragma unroll
            for (int mt = 0; mt < 2; mt++)
                #pragma unroll
                for (int nt = 0; nt < 4; nt++) {
                    int m0 = mt * 16 + g8, n0 = nt * 8 + q * 2;
                    *(float2*)&zb[(w * 32 + m0) * 34 + n0] =
                        make_float2(acc[mt][nt][0], acc[mt][nt][1]);
                    *(float2*)&zb[(w * 32 + m0 + 8) * 34 + n0] =
                        make_float2(acc[mt][nt][2], acc[mt][nt][3]);
                }
        }
        __syncthreads();

        // ---- epilogue: thread = (hl, b) ----
        int t = dir ? 255 - step : step;
        int m = t * 32 + b;
        float z[4];
        #pragma unroll
        for (int g = 0; g < 4; g++) {
            int r = g * 8 + hl;
            float s = 0.0f;
            #pragma unroll
            for (int sl = 0; sl < 8; sl++) s += zb[(sl * 32 + r) * 34 + b];
            z[g] = s + preg[g];
        }
        float c = sigf(z[1]) * creg + sigf(z[0]) * tanhf(z[2]);
        float hn = sigf(z[3]) * tanhf(c);
        creg = c;
        int h = h0 + hl;
        __nv_bfloat16 bh2 = __float2bfloat16(hn);
        __nv_bfloat16 bl2 = __float2bfloat16(hn - __bfloat162float(bh2));
        {
            unsigned short* hdst = hbf + nbuf * 65536 + dir * 32768;
            st_cg_u16(hdst + h * 32 + b, __bfloat16_as_ushort(bh2));
            st_cg_u16(hdst + 16384 + h * 32 + b, __bfloat16_as_ushort(bl2));
        }
        __syncthreads();             // all h stores done before arrive

        if (tid == 0 && step < 255) st_rel(&flg[slot], (unsigned)(step + 1));

        // overlap split-output stores + next-pre prefetch with the wait
        outh[(dir * 512 + h) * NS + m] = bh2;
        outl[(dir * 512 + h) * NS + m] = bl2;
        {
            int tn = dir ? 255 - (step + 1) : (step + 1);
            if (step == 255) tn = t;
            int mn = tn * 32 + b;
            #pragma unroll
            for (int g = 0; g < 4; g++) preg[g] = __ldg(&pre[(g * 512 + h0 + hl) * NS + mn]);
        }
        if (step < 255) {
            if (tid < 32) {
                unsigned target = (unsigned)(step + 1);
                for (;;) {
                    unsigned v0 = ld_acq(&flg[tid]);
                    unsigned v1 = ld_acq(&flg[32 + tid]);
                    if (__all_sync(0xffffffffu, (v0 >= target) && (v1 >= target))) break;
                }
            }
            __syncthreads();
        }
        buf = nbuf;
    }
}

// ---------------- lin2: 4 m per block, transposed W in smem ----------------
__global__ void lin2_kernel(const float* __restrict__ h1, const float* __restrict__ W,
                            const float* __restrict__ bias, float* __restrict__ em) {
    __shared__ float Wt[128 * 18];
    __shared__ float rows[4][128];
    int tid = threadIdx.x, lane = tid & 31, w = tid >> 5;
    for (int idx = tid; idx < 2304; idx += 128) {
        int o = idx >> 7, k = idx & 127;
        Wt[k * 18 + o] = W[idx];
    }
    int mm = blockIdx.x * 4 + w;
    for (int i = lane; i < 128; i += 32) rows[w][i] = h1[i * NS + mm];
    __syncthreads();
    if (lane < 18) {
        float acc = bias[lane];
        #pragma unroll 8
        for (int k = 0; k < 128; k++) acc += rows[w][k] * Wt[k * 18 + lane];
        int s = mm >> 5, b = mm & 31;
        em[(b * 256 + s) * 18 + lane] = acc;
    }
}

// ---------------- CRF ----------------
__global__ void crf_kernel(const float* __restrict__ em, const int* __restrict__ y,
                           const float* __restrict__ cstart, const float* __restrict__ cend,
                           const float* __restrict__ ctrans,
                           float* __restrict__ dec_out, float* __restrict__ perb) {
    __shared__ float tr[324];
    __shared__ float sc[18], fs[18];
    __shared__ int hist[255][18];
    __shared__ int dec[256];
    int b = blockIdx.x, j = threadIdx.x;
    for (int i = j; i < 324; i += 32) tr[i] = ctrans[i];
    const float* emb = em + b * 256 * 18;
    if (j < 18) { float v = cstart[j] + emb[j]; sc[j] = v; fs[j] = v; }
    __syncwarp();
    for (int s = 1; s < 256; s++) {
        float bestv = -1e30f, m = -1e30f, e = 0.0f, ssum = 0.0f;
        int bi = 0;
        if (j < 18) {
            e = emb[s * 18 + j];
            #pragma unroll
            for (int i = 0; i < 18; i++) {
                float t1 = sc[i] + tr[i * 18 + j];
                if (t1 > bestv) { bestv = t1; bi = i; }
                float t2 = fs[i] + tr[i * 18 + j];
                m = fmaxf(m, t2);
            }
            #pragma unroll
            for (int i = 0; i < 18; i++) ssum += __expf(fs[i] + tr[i * 18 + j] - m);
        }
        __syncwarp();
        if (j < 18) {
            sc[j] = bestv + e;
            fs[j] = m + __logf(ssum) + e;
            hist[s - 1][j] = bi;
        }
        __syncwarp();
    }
    float v = (j < 18) ? fs[j] + cend[j] : -1e30f;
    float m = v;
    for (int o = 16; o; o >>= 1) m = fmaxf(m, __shfl_xor_sync(0xffffffffu, m, o));
    float ex = (j < 18) ? __expf(v - m) : 0.0f;
    for (int o = 16; o; o >>= 1) ex += __shfl_xor_sync(0xffffffffu, ex, o);
    float logZ = m + __logf(ex);

    if (j == 0) {
        float best = -1e30f; int last = 0;
        for (int t2 = 0; t2 < 18; t2++) {
            float vv = sc[t2] + cend[t2];
            if (vv > best) { best = vv; last = t2; }
        }
        dec[255] = last;
        int tag = last;
        for (int s = 254; s >= 0; s--) { tag = hist[s][tag]; dec[s] = tag; }
        const int* yb = y + b * 256;
        float num = cstart[yb[0]] + emb[yb[0]];
        for (int s = 1; s < 256; s++) num += tr[yb[s-1] * 18 + yb[s]] + emb[s * 18 + yb[s]];
        num += cend[yb[255]];
        perb[b] = num - logZ;
    }
    __syncwarp();
    for (int s = j; s < 256; s += 32) dec_out[b * 256 + s] = (float)dec[s];
}

__global__ void loss_kernel(const float* __restrict__ perb, float* __restrict__ lossp) {
    if (threadIdx.x == 0) {
        float s = 0.0f;
        for (int b = 0; b < 32; b++) s += perb[b];
        *lossp = -s / 8192.0f;
    }
}

// ---------------- launch ----------------
extern "C" void kernel_launch(void* const* d_in, const int* in_sizes, int n_in,
                              void* d_out, int out_size) {
    (void)in_sizes; (void)n_in; (void)out_size;
    const int*   xw   = (const int*)d_in[0];
    const float* xpos = (const float*)d_in[1];
    const int*   xch  = (const int*)d_in[2];
    const float* xenr = (const float*)d_in[3];
    /* d_in[4] = mask (all ones, folded out) */
    const int*   yw   = (const int*)d_in[5];
    const float* wemb = (const float*)d_in[6];
    const float* cemb = (const float*)d_in[7];
    const float* cnnW = (const float*)d_in[8];
    const float* cnnb = (const float*)d_in[9];
    const float* lin1W = (const float*)d_in[10];
    const float* lin1b = (const float*)d_in[11];
    const float* lin2W = (const float*)d_in[12];
    const float* lin2b = (const float*)d_in[13];
    const float* cst  = (const float*)d_in[14];
    const float* cen  = (const float*)d_in[15];
    const float* ctr  = (const float*)d_in[16];
    const float* w0fI = (const float*)d_in[17];
    const float* w0fH = (const float*)d_in[18];
    const float* b0f  = (const float*)d_in[19];
    const float* w0bI = (const float*)d_in[20];
    const float* w0bH = (const float*)d_in[21];
    const float* b0b  = (const float*)d_in[22];
    const float* w1fI = (const float*)d_in[23];
    const float* w1fH = (const float*)d_in[24];
    const float* b1f  = (const float*)d_in[25];
    const float* w1bI = (const float*)d_in[26];
    const float* w1bH = (const float*)d_in[27];
    const float* b1b  = (const float*)d_in[28];
    float* out = (float*)d_out;

    cudaFuncSetAttribute(lstm_persistent, cudaFuncAttributeMaxDynamicSharedMemorySize, LSTM_SMEM);
    cudaFuncSetAttribute(bgemm, cudaFuncAttributeMaxDynamicSharedMemorySize, GEMM_SMEM);

    float *pF, *pB, *ph1, *pperb;
    cudaGetSymbolAddress((void**)&pF,    g_preF);
    cudaGetSymbolAddress((void**)&pB,    g_preB);
    cudaGetSymbolAddress((void**)&ph1,   g_h1);
    cudaGetSymbolAddress((void**)&pperb, g_perb);
    __nv_bfloat16 *pwah, *pwal, *pwbh, *pwbl, *pxh, *pxl;
    cudaGetSymbolAddress((void**)&pwah, g_wah);
    cudaGetSymbolAddress((void**)&pwal, g_wal);
    cudaGetSymbolAddress((void**)&pwbh, g_wbh);
    cudaGetSymbolAddress((void**)&pwbl, g_wbl);
    cudaGetSymbolAddress((void**)&pxh,  g_xh);
    cudaGetSymbolAddress((void**)&pxl,  g_xl);

    embed_cnn_kernel<<<NS, 128>>>(xw, xpos, xch, xenr, wemb, cemb, cnnW, cnnb);
    pad_x<<<672, 256>>>();

    // ---- layer0 input projections (K=331 -> Kp=352) ----
    cvt_w<<<dim3(2, 2048), 256>>>(w0fI, pwah, pwal, IN0, IN0P);
    cvt_w<<<dim3(2, 2048), 256>>>(w0bI, pwbh, pwbl, IN0, IN0P);
    bgemm<<<dim3(64, 16, 2), 256, GEMM_SMEM>>>(pwah, pwal, b0f, pF, pwbh, pwbl, b0b, pB, NS, IN0P);
    lstm_reset<<<32, 1024>>>();
    lstm_persistent<<<128, 256, LSTM_SMEM>>>(pF, pB, w0fH, w0bH, pxh, pxl);

    // ---- layer1 input projections (K=1024); X = layer0 h (already split) ----
    cvt_w<<<dim3(4, 2048), 256>>>(w1fI, pwah, pwal, 1024, 1024);
    cvt_w<<<dim3(4, 2048), 256>>>(w1bI, pwbh, pwbl, 1024, 1024);
    bgemm<<<dim3(64, 16, 2), 256, GEMM_SMEM>>>(pwah, pwal, b1f, pF, pwbh, pwbl, b1b, pB, NS, 1024);
    lstm_reset<<<32, 1024>>>();
    lstm_persistent<<<128, 256, LSTM_SMEM>>>(pF, pB, w1fH, w1bH, pxh, pxl);

    // ---- heads; X = layer1 h (already split) ----
    cvt_w<<<dim3(4, 128), 256>>>(lin1W, pwah, pwal, 1024, 1024);
    bgemm<<<dim3(64, 1, 1), 256, GEMM_SMEM>>>(pwah, pwal, lin1b, ph1, pwah, pwal, lin1b, ph1, NS, 1024);
    lin2_kernel<<<2048, 128>>>(ph1, lin2W, lin2b, out);

    // CRF: em at out[0..147456), decoded at out[147456..155648), loss at out[155648]
    crf_kernel<<<32, 32>>>(out, yw, cst, cen, ctr, out + 147456, pperb);
    loss_kernel<<<1, 32>>>(pperb, out + 147456 + 8192);
}